// round 12
// baseline (speedup 1.0000x reference)
#include <cuda_runtime.h>
#include <cuda_fp16.h>
#include <math.h>
#include <cstdint>

#define T_STEPS 240
#define BATCH   240
#define MPAD    256
#define INPUTD  256
#define HID     1024
#define NSTEPS  30
#define OUTD    8
#define WW      240
#define KTOT    1280
#define KCH     64
#define NCTA    128
#define NCTA_D  64

// encoder smem: W resident 20 chunks x 8KB = 160KB, A ring 3 x 16KB
#define SMW     163840
#define SMEMB   (SMW + 3 * 16384)

// ---------------------------------------------------------------------------
// helpers
// ---------------------------------------------------------------------------
__device__ __forceinline__ uint32_t smem_to_u32(const void* p) {
    uint32_t a;
    asm("{ .reg .u64 t; cvta.to.shared.u64 t, %1; cvt.u32.u64 %0, t; }" : "=r"(a) : "l"(p));
    return a;
}

#define CP_ASYNC16(dst, src) \
    asm volatile("cp.async.cg.shared.global [%0], [%1], 16;" \
                 :: "r"(dst), "l"(__cvta_generic_to_global(src)))
#define CP_COMMIT() asm volatile("cp.async.commit_group;" ::: "memory")
#define CP_WAIT1()  asm volatile("cp.async.wait_group 1;" ::: "memory")
#define CP_WAIT0()  asm volatile("cp.async.wait_group 0;" ::: "memory")

#define LDSM4(r, addr) \
    asm volatile("ldmatrix.sync.aligned.m8n8.x4.shared.b16 {%0,%1,%2,%3}, [%4];" \
                 : "=r"((r)[0]), "=r"((r)[1]), "=r"((r)[2]), "=r"((r)[3]) : "r"(addr))

#define MMA16816(d, a, b) \
    asm volatile("mma.sync.aligned.m16n8k16.row.col.f32.f16.f16.f32 " \
                 "{%0,%1,%2,%3}, {%4,%5,%6,%7}, {%8,%9}, {%0,%1,%2,%3};" \
                 : "+f"((d)[0]), "+f"((d)[1]), "+f"((d)[2]), "+f"((d)[3]) \
                 : "r"((a)[0]), "r"((a)[1]), "r"((a)[2]), "r"((a)[3]), \
                   "r"((b)[0]), "r"((b)[1]))

// ---------------------------------------------------------------------------
// device scratch
// ---------------------------------------------------------------------------
__device__ __align__(256) __half g_W[4096 * KTOT];
__device__ __align__(256) __half g_x[(size_t)T_STEPS * MPAD * INPUTD];
__device__ __align__(256) __half g_h[2][MPAD * HID];
__device__ __align__(16) float g_bias[4 * HID];

// decoder fp16 weights
__device__ __align__(256) __half g_attnWh[WW * HID];
__device__ __align__(256) __half g_combWh[HID * HID];
__device__ __align__(256) __half g_gWih16[3 * HID * HID];
__device__ __align__(256) __half g_gWhh16[3 * HID * HID];
__device__ __align__(256) __half g_ctxT[(size_t)HID * WW];

__device__ __align__(16) float g_u[OUTD];
__device__ __align__(16) float g_hdec[HID];
__device__ __align__(16) float g_comb[HID];
__device__ __align__(16) float g_gi[3 * HID];
__device__ __align__(16) float g_gh[3 * HID];
__device__ __align__(16) float g_v2[HID + OUTD];   // [u; applied]
__device__ float g_sch[WW];

// producer->consumer flags: g_hflag[mhalf][kgroup], monotonic (4 CTAs/group/step)
__device__ unsigned g_hflag[2][16];

__device__ unsigned g_bcnt = 0;
__device__ volatile unsigned g_bgen = 0;

__device__ __forceinline__ void gbar(unsigned nctas) {
    __syncthreads();
    if (threadIdx.x == 0) {
        __threadfence();
        unsigned gen = g_bgen;
        if (atomicAdd(&g_bcnt, 1u) == nctas - 1u) {
            g_bcnt = 0;
            __threadfence();
            g_bgen = gen + 1u;
        } else {
            while (g_bgen == gen) __nanosleep(32);
        }
        __threadfence();
    }
    __syncthreads();
}

__device__ __forceinline__ void wait_flag(const unsigned* f, unsigned target) {
    volatile const unsigned* vf = (volatile const unsigned*)f;
    while (*vf < target) __nanosleep(20);
    __threadfence();
}

__device__ __forceinline__ float sigf(float x)  { return __fdividef(1.f, 1.f + __expf(-x)); }
__device__ __forceinline__ float tanhf_fast(float x) { return 1.f - __fdividef(2.f, __expf(2.f * x) + 1.f); }
__device__ __forceinline__ float warp_red(float s) {
#pragma unroll
    for (int o = 16; o; o >>= 1) s += __shfl_down_sync(0xffffffffu, s, o);
    return s;
}

// fp16-weight x fp32-vector dot, length 1024, lane-strided
__device__ __forceinline__ float dot1024(const __half* __restrict__ w,
                                         const float* __restrict__ v, int lane) {
    float s = 0.f;
    const uint4* w4 = (const uint4*)w;
#pragma unroll
    for (int k = lane; k < 128; k += 32) {
        uint4 u = w4[k];
        const float4* vv = (const float4*)(v + (k << 3));
        float4 va = vv[0], vb = vv[1];
        float2 f0 = __half22float2(*(__half2*)&u.x);
        float2 f1 = __half22float2(*(__half2*)&u.y);
        float2 f2 = __half22float2(*(__half2*)&u.z);
        float2 f3 = __half22float2(*(__half2*)&u.w);
        s += f0.x * va.x + f0.y * va.y + f1.x * va.z + f1.y * va.w
           + f2.x * vb.x + f2.y * vb.y + f3.x * vb.z + f3.y * vb.w;
    }
    return s;
}

// ---------------------------------------------------------------------------
// fragment machinery (32m x 32n warp tile, single-pass fp16)
// ---------------------------------------------------------------------------
struct Frag {
    uint32_t ah[2][4], bh[4][2];
};

__device__ __forceinline__ void load_frags(Frag& f, uint32_t Ah, uint32_t Bh,
                                           int ks, int wr, int wc, int lane) {
#pragma unroll
    for (int mt = 0; mt < 2; mt++) {
        int r = wr * 32 + mt * 16 + (lane & 15);
        uint32_t ch = ((uint32_t)((ks * 2 + (lane >> 4)) ^ (r & 7))) << 4;
        LDSM4(f.ah[mt], Ah + r * 128 + ch);
    }
#pragma unroll
    for (int gp = 0; gp < 2; gp++) {
        int rn = (gp * 2 + (lane >> 4)) * 16 + wc * 8 + (lane & 7);
        uint32_t ch = ((uint32_t)((ks * 2 + ((lane >> 3) & 1)) ^ (rn & 7))) << 4;
        LDSM4(&f.bh[gp * 2][0], Bh + rn * 128 + ch);
    }
}

__device__ __forceinline__ void do_mmas(float (&acc)[2][4][4], const Frag& f) {
#pragma unroll
    for (int mt = 0; mt < 2; mt++)
#pragma unroll
        for (int q = 0; q < 4; q++)
            MMA16816(acc[mt][q], f.ah[mt], f.bh[q]);
}

// ---------------------------------------------------------------------------
// init / convert
// ---------------------------------------------------------------------------
__global__ void k_init(const float* __restrict__ bih, const float* __restrict__ bhh) {
    int i = blockIdx.x * blockDim.x + threadIdx.x;
    int n = MPAD * HID;
    __half z = __float2half(0.f);
    for (int j = i; j < n; j += gridDim.x * blockDim.x) {
        g_h[0][j] = z; g_h[1][j] = z;
    }
    if (i < 4 * HID) g_bias[i] = bih[i] + bhh[i];
    if (i < 32) g_hflag[i >> 4][i & 15] = 0;   // reset flags (graph replay!)
}

__global__ void k_conv_w(const float* __restrict__ Whh, const float* __restrict__ Wih) {
    size_t i = (size_t)blockIdx.x * blockDim.x + threadIdx.x;
    if (i >= (size_t)4096 * KTOT) return;
    int r = (int)(i / KTOT);
    int k = (int)(i % KTOT);
    float v = (k < HID) ? Whh[(size_t)r * HID + k] : Wih[(size_t)r * INPUTD + (k - HID)];
    g_W[i] = __float2half(v);
}

__global__ void k_conv_x(const float* __restrict__ data) {
    size_t i = (size_t)blockIdx.x * blockDim.x + threadIdx.x;
    if (i >= (size_t)T_STEPS * MPAD * INPUTD) return;
    int k = (int)(i % INPUTD);
    int b = (int)((i / INPUTD) % MPAD);
    int t = (int)(i / ((size_t)MPAD * INPUTD));
    float v = (b < BATCH) ? data[((size_t)t * BATCH + b) * INPUTD + k] : 0.f;
    g_x[i] = __float2half(v);
}

__global__ void k_conv_dec(const float* __restrict__ attn_W, const float* __restrict__ comb_W,
                           const float* __restrict__ gWih, const float* __restrict__ gWhh) {
    size_t i = (size_t)blockIdx.x * blockDim.x + threadIdx.x;
    const size_t nA = (size_t)WW * HID;
    const size_t nC = (size_t)HID * HID;
    const size_t nG = (size_t)3 * HID * HID;
    if (i < nA) {
        size_t j = i / HID, k = i % HID;
        g_attnWh[i] = __float2half(attn_W[j * (HID + OUTD) + OUTD + k]);
        return;
    }
    i -= nA;
    if (i < nC) {
        size_t r = i / HID, k = i % HID;
        g_combWh[i] = __float2half(comb_W[r * (HID + OUTD) + OUTD + k]);
        return;
    }
    i -= nC;
    if (i < nG) { g_gWih16[i] = __float2half(gWih[i]); return; }
    i -= nG;
    if (i < nG) { g_gWhh16[i] = __float2half(gWhh[i]); return; }
}

// ---------------------------------------------------------------------------
// k_enc: persistent, 240 LSTM steps, weights resident, c in registers.
// NO grid barrier: per-kgroup producer flags (wait on 4 CTAs, not 64).
// ---------------------------------------------------------------------------
__global__ __launch_bounds__(256, 1) void k_enc() {
    extern __shared__ __align__(128) char smem[];
    const uint32_t sb  = smem_to_u32(smem);
    const uint32_t sbW = sb;
    const uint32_t sbA = sb + SMW;
    const int tid  = threadIdx.x;
    const int lane = tid & 31;
    const int wid  = tid >> 5;
    const int wr   = wid & 3;
    const int wc   = wid >> 2;
    const int n0   = (blockIdx.x & 63) * 16;
    const int mh   = blockIdx.x >> 6;
    const int m0   = mh * 128;
    const int grp  = (blockIdx.x & 63) >> 2;   // our k-group (n0/64)
    const int rowq = lane >> 2;
    const int col2 = (lane & 3) * 2;

    // resident W: 20 chunks x (64 rows x 64 k) = 160 KB
    for (int i = tid; i < 10240; i += 256) {
        int ci = i >> 9, r = (i >> 3) & 63, ch = i & 7;
        int wrow = (r >> 4) * HID + n0 + (r & 15);
        size_t off = (size_t)wrow * KTOT + ci * 64 + ch * 8;
        uint32_t dst = sbW + ci * 8192 + r * 128 + (((uint32_t)(ch ^ (r & 7))) << 4);
        CP_ASYNC16(dst, g_W + off);
    }
    CP_COMMIT();

    int lb = 0, cbuf = 0;

    auto loadX = [&](int t, int j) {
        uint32_t base = sbA + lb * 16384; lb = (lb == 2) ? 0 : lb + 1;
#pragma unroll
        for (int i = tid; i < 1024; i += 256) {
            int r = i >> 3, ch = i & 7;
            size_t off = ((size_t)t * MPAD + m0 + r) * INPUTD + j * 64 + ch * 8;
            CP_ASYNC16(base + r * 128 + (((uint32_t)(ch ^ (r & 7))) << 4), g_x + off);
        }
        CP_COMMIT();
    };
    auto loadH = [&](const __half* hIn, int c) {
        uint32_t base = sbA + lb * 16384; lb = (lb == 2) ? 0 : lb + 1;
#pragma unroll
        for (int i = tid; i < 1024; i += 256) {
            int r = i >> 3, ch = i & 7;
            size_t off = (size_t)(m0 + r) * HID + c * 64 + ch * 8;
            CP_ASYNC16(base + r * 128 + (((uint32_t)(ch ^ (r & 7))) << 4), hIn + off);
        }
        CP_COMMIT();
    };

    float acc[2][4][4];
    float creg[2][2][2];
#pragma unroll
    for (int a = 0; a < 2; a++)
#pragma unroll
        for (int b = 0; b < 2; b++)
#pragma unroll
            for (int d = 0; d < 2; d++) creg[a][b][d] = 0.f;
#pragma unroll
    for (int mt = 0; mt < 2; mt++)
#pragma unroll
        for (int q = 0; q < 4; q++)
#pragma unroll
            for (int j = 0; j < 4; j++) acc[mt][q][j] = 0.f;

    auto computeChunk = [&](int wchunk) {
        uint32_t Ah = sbA + cbuf * 16384; cbuf = (cbuf == 2) ? 0 : cbuf + 1;
        uint32_t Bh = sbW + wchunk * 8192;
        Frag fr[2];
        load_frags(fr[0], Ah, Bh, 0, wr, wc, lane);
#pragma unroll
        for (int ks = 0; ks < 4; ks++) {
            if (ks < 3) load_frags(fr[(ks + 1) & 1], Ah, Bh, ks + 1, wr, wc, lane);
            do_mmas(acc, fr[ks & 1]);
        }
    };

    // prologue: x chunks 0,1 of step 0
    loadX(0, 0); loadX(0, 1);

    for (int t = 0; t < T_STEPS; t++) {
        const __half* __restrict__ hIn = g_h[t & 1];
        const unsigned tgt = 4u * (unsigned)t;

        // ---- x phase (weight chunks 16..19); interleave first h waits ----
        CP_WAIT1(); __syncthreads(); loadX(t, 2); computeChunk(16);
        CP_WAIT1(); __syncthreads(); loadX(t, 3); computeChunk(17);
        CP_WAIT1(); __syncthreads();
        wait_flag(&g_hflag[mh][0], tgt); loadH(hIn, 0); computeChunk(18);
        CP_WAIT1(); __syncthreads();
        wait_flag(&g_hflag[mh][1], tgt); loadH(hIn, 1); computeChunk(19);

        // ---- h phase (weight chunks 0..15), per-group flag waits ----
        for (int c = 0; c < 16; c++) {
            CP_WAIT1(); __syncthreads();
            if (c < 14) {
                wait_flag(&g_hflag[mh][c + 2], tgt);
                loadH(hIn, c + 2);
            } else if (t + 1 < T_STEPS) {
                loadX(t + 1, c - 14);   // prefetch next step's x
            }
            computeChunk(c);
        }

        // ---- fused LSTM gate epilogue (c in registers) ----
        __half* __restrict__ hOut = g_h[(t + 1) & 1];
#pragma unroll
        for (int mt = 0; mt < 2; mt++)
#pragma unroll
            for (int rp = 0; rp < 2; rp++) {
                int m = m0 + wr * 32 + mt * 16 + rowq + rp * 8;
                if (m < BATCH) {
                    int n = n0 + wc * 8 + col2;
                    size_t idx = (size_t)m * HID + n;
                    float2 bi = *(const float2*)&g_bias[n];
                    float2 bf = *(const float2*)&g_bias[HID + n];
                    float2 bg = *(const float2*)&g_bias[2 * HID + n];
                    float2 bo = *(const float2*)&g_bias[3 * HID + n];
                    float h[2];
#pragma unroll
                    for (int j = 0; j < 2; j++) {
                        float gi = acc[mt][0][rp * 2 + j] + (j ? bi.y : bi.x);
                        float gf = acc[mt][1][rp * 2 + j] + (j ? bf.y : bf.x);
                        float gg = acc[mt][2][rp * 2 + j] + (j ? bg.y : bg.x);
                        float go = acc[mt][3][rp * 2 + j] + (j ? bo.y : bo.x);
                        float cn = sigf(gf) * creg[mt][rp][j] + sigf(gi) * tanhf_fast(gg);
                        creg[mt][rp][j] = cn;
                        h[j] = sigf(go) * tanhf_fast(cn);
                    }
                    *(__half2*)&hOut[idx] =
                        __halves2half2(__float2half(h[0]), __float2half(h[1]));
                }
            }

        // publish h(t+1) for our k-group
        __threadfence();
        __syncthreads();
        if (tid == 0) atomicAdd(&g_hflag[mh][grp], 1u);

        // reset accumulators for next step
#pragma unroll
        for (int mt = 0; mt < 2; mt++)
#pragma unroll
            for (int q = 0; q < 4; q++)
#pragma unroll
                for (int j = 0; j < 4; j++) acc[mt][q][j] = 0.f;
    }
}

// ---------------------------------------------------------------------------
// k_dec: persistent decoder, 64 CTAs x 256 thr, 5 barriers/step, fp16 weights.
// ---------------------------------------------------------------------------
__global__ __launch_bounds__(256, 1) void k_dec(
    const float* __restrict__ attn_W, const float* __restrict__ attn_b,
    const float* __restrict__ comb_W, const float* __restrict__ comb_b,
    const float* __restrict__ gbih,   const float* __restrict__ gbhh,
    const float* __restrict__ out_W,  const float* __restrict__ out_b,
    float* __restrict__ outp)
{
    __shared__ float s_aw[WW];
    __shared__ float rbuf[8];
    __shared__ float lg[OUTD];

    const int tid  = threadIdx.x;
    const int bid  = blockIdx.x;
    const int lane = tid & 31;
    const int warp = tid >> 5;
    const int gw   = bid * 8 + warp;   // 0..511
    const int gt   = bid * 256 + tid;  // 0..16383

    // init: hdec, u, transposed ctx
    if (gt < HID) g_hdec[gt] = __half2float(g_h[0][(size_t)(BATCH - 1) * HID + gt]);
    if (gt < OUTD) g_u[gt] = 0.125f;
    for (size_t i = gt; i < (size_t)WW * HID; i += NCTA_D * 256) {
        size_t j = i / HID, n = i % HID;
        g_ctxT[n * WW + j] = g_h[0][j * HID + n];
    }
    gbar(NCTA_D);

    auto out_head = [&](int sidx) {
        if (warp < OUTD) {
            const float4* row = (const float4*)(out_W + (size_t)warp * HID);
            const float4* v   = (const float4*)g_hdec;
            float s = 0.f;
            for (int k = lane; k < HID / 4; k += 32) {
                float4 w = row[k], x = v[k];
                s += w.x * x.x + w.y * x.y + w.z * x.z + w.w * x.w;
            }
            s = warp_red(s);
            if (!lane) lg[warp] = s + out_b[warp];
        }
        __syncthreads();
        if (tid == 0) {
            float mx = -1e30f;
#pragma unroll
            for (int i = 0; i < OUTD; i++) mx = fmaxf(mx, lg[i]);
            float sum = 0.f;
#pragma unroll
            for (int i = 0; i < OUTD; i++) sum += __expf(lg[i] - mx);
            float lse = mx + __logf(sum);
#pragma unroll
            for (int i = 0; i < OUTD; i++) {
                float lp = lg[i] - lse;
                outp[sidx * OUTD + i] = lp;
                g_u[i] = lp;
            }
        }
        __syncthreads();
    };

    for (int s = 0; s < NSTEPS; s++) {
        // P1: CTA0 -> prev-step output head (writes u); others -> attn score_h
        if (bid == 0) {
            if (s > 0) out_head(s - 1);
        } else {
            int j = gw - 8;
            if (j < WW) {
                float x = dot1024(g_attnWh + (size_t)j * HID, g_hdec, lane);
                x = warp_red(x);
                if (!lane) g_sch[j] = x;
            }
        }
        gbar(NCTA_D);

        // P2: per-CTA redundant softmax + applied columns
        {
            float x;
            if (tid < WW) {
                float su = 0.f;
#pragma unroll
                for (int k = 0; k < OUTD; k++)
                    su += g_u[k] * attn_W[(size_t)tid * (HID + OUTD) + k];
                x = g_sch[tid] + su + attn_b[tid];
            } else x = -1e30f;
            float mx = x;
#pragma unroll
            for (int o = 16; o; o >>= 1) mx = fmaxf(mx, __shfl_xor_sync(0xffffffffu, mx, o));
            if (!lane) rbuf[warp] = mx;
            __syncthreads();
            float bm = rbuf[0];
#pragma unroll
            for (int i = 1; i < 8; i++) bm = fmaxf(bm, rbuf[i]);
            float e = (tid < WW) ? __expf(x - bm) : 0.f;
            float sm = e;
#pragma unroll
            for (int o = 16; o; o >>= 1) sm += __shfl_xor_sync(0xffffffffu, sm, o);
            __syncthreads();
            if (!lane) rbuf[warp] = sm;
            __syncthreads();
            float tot = 0.f;
#pragma unroll
            for (int i = 0; i < 8; i++) tot += rbuf[i];
            if (tid < WW) s_aw[tid] = e / tot;
            __syncthreads();
#pragma unroll
            for (int rep = 0; rep < 2; rep++) {
                int n = bid * 8 + warp + rep * 512;
                const __half* ct = g_ctxT + (size_t)n * WW;
                float a = 0.f;
                for (int j = lane; j < WW; j += 32) a += s_aw[j] * __half2float(ct[j]);
                a = warp_red(a);
                if (!lane) g_v2[OUTD + n] = a;
            }
            if (bid == 0 && tid < OUTD) g_v2[tid] = g_u[tid];
        }
        gbar(NCTA_D);

        // P3: comb = relu(comb_W @ [u; applied] + b)
#pragma unroll
        for (int rep = 0; rep < 2; rep++) {
            int r = gw + rep * 512;
            float x = dot1024(g_combWh + (size_t)r * HID, g_v2 + OUTD, lane);
            x = warp_red(x);
            if (!lane) {
                float su = 0.f;
#pragma unroll
                for (int k = 0; k < OUTD; k++)
                    su += comb_W[(size_t)r * (HID + OUTD) + k] * g_v2[k];
                g_comb[r] = fmaxf(x + su + comb_b[r], 0.f);
            }
        }
        gbar(NCTA_D);

        // P4: gi / gh (6144 rows over 512 warps)
        for (int rr = gw; rr < 6 * HID; rr += 512) {
            float x;
            if (rr < 3 * HID) x = dot1024(g_gWih16 + (size_t)rr * HID, g_comb, lane);
            else              x = dot1024(g_gWhh16 + (size_t)(rr - 3 * HID) * HID, g_hdec, lane);
            x = warp_red(x);
            if (!lane) {
                if (rr < 3 * HID) g_gi[rr] = x + gbih[rr];
                else              g_gh[rr - 3 * HID] = x + gbhh[rr - 3 * HID];
            }
        }
        gbar(NCTA_D);

        // P5: distributed hdec update
        if (tid < 16) {
            int n = bid * 16 + tid;
            float r  = sigf(g_gi[n] + g_gh[n]);
            float z  = sigf(g_gi[HID + n] + g_gh[HID + n]);
            float nn = tanhf_fast(g_gi[2 * HID + n] + r * g_gh[2 * HID + n]);
            g_hdec[n] = (1.f - z) * nn + z * g_hdec[n];
        }
        gbar(NCTA_D);
    }

    // final output head
    if (bid == 0) out_head(NSTEPS - 1);
}

// ---------------------------------------------------------------------------
// launch
// ---------------------------------------------------------------------------
extern "C" void kernel_launch(void* const* d_in, const int* in_sizes, int n_in,
                              void* d_out, int out_size) {
    const float* data     = (const float*)d_in[0];
    const float* enc_Wih  = (const float*)d_in[1];
    const float* enc_Whh  = (const float*)d_in[2];
    const float* enc_bih  = (const float*)d_in[3];
    const float* enc_bhh  = (const float*)d_in[4];
    const float* attn_W   = (const float*)d_in[5];
    const float* attn_b   = (const float*)d_in[6];
    const float* comb_W   = (const float*)d_in[7];
    const float* comb_b   = (const float*)d_in[8];
    const float* gru_Wih  = (const float*)d_in[9];
    const float* gru_Whh  = (const float*)d_in[10];
    const float* gru_bih  = (const float*)d_in[11];
    const float* gru_bhh  = (const float*)d_in[12];
    const float* out_W    = (const float*)d_in[13];
    const float* out_b    = (const float*)d_in[14];
    float* out = (float*)d_out;

    cudaFuncSetAttribute(k_enc, cudaFuncAttributeMaxDynamicSharedMemorySize, SMEMB);

    k_init<<<1024, 256>>>(enc_bih, enc_bhh);
    k_conv_w<<<(4096 * KTOT + 255) / 256, 256>>>(enc_Whh, enc_Wih);
    k_conv_x<<<(T_STEPS * MPAD * INPUTD + 255) / 256, 256>>>(data);
    {
        size_t ntot = (size_t)WW * HID + (size_t)HID * HID + 2 * (size_t)3 * HID * HID;
        k_conv_dec<<<(int)((ntot + 255) / 256), 256>>>(attn_W, comb_W, gru_Wih, gru_Whh);
    }

    k_enc<<<NCTA, 256, SMEMB>>>();

    k_dec<<<NCTA_D, 256>>>(attn_W, attn_b, comb_W, comb_b,
                           gru_bih, gru_bhh, out_W, out_b, out);
}

// round 13
// speedup vs baseline: 1.6047x; 1.6047x over previous
#include <cuda_runtime.h>
#include <cuda_fp16.h>
#include <math.h>
#include <cstdint>

#define T_STEPS 240
#define BATCH   240
#define MPAD    256
#define INPUTD  256
#define HID     1024
#define NSTEPS  30
#define OUTD    8
#define WW      240
#define KTOT    1280
#define NCTA    128
#define NCTA_D  64

// encoder smem: W resident 160KB + A ring 2 x 32KB = 224KB
#define SMW     163840
#define SMEMB   (SMW + 2 * 32768)

// ---------------------------------------------------------------------------
// helpers
// ---------------------------------------------------------------------------
__device__ __forceinline__ uint32_t smem_to_u32(const void* p) {
    uint32_t a;
    asm("{ .reg .u64 t; cvta.to.shared.u64 t, %1; cvt.u32.u64 %0, t; }" : "=r"(a) : "l"(p));
    return a;
}

#define CP_ASYNC16(dst, src) \
    asm volatile("cp.async.cg.shared.global [%0], [%1], 16;" \
                 :: "r"(dst), "l"(__cvta_generic_to_global(src)))
#define CP_COMMIT() asm volatile("cp.async.commit_group;" ::: "memory")
#define CP_WAIT1()  asm volatile("cp.async.wait_group 1;" ::: "memory")
#define CP_WAIT0()  asm volatile("cp.async.wait_group 0;" ::: "memory")

#define LDSM4(r, addr) \
    asm volatile("ldmatrix.sync.aligned.m8n8.x4.shared.b16 {%0,%1,%2,%3}, [%4];" \
                 : "=r"((r)[0]), "=r"((r)[1]), "=r"((r)[2]), "=r"((r)[3]) : "r"(addr))

#define MMA16816(d, a, b) \
    asm volatile("mma.sync.aligned.m16n8k16.row.col.f32.f16.f16.f32 " \
                 "{%0,%1,%2,%3}, {%4,%5,%6,%7}, {%8,%9}, {%0,%1,%2,%3};" \
                 : "+f"((d)[0]), "+f"((d)[1]), "+f"((d)[2]), "+f"((d)[3]) \
                 : "r"((a)[0]), "r"((a)[1]), "r"((a)[2]), "r"((a)[3]), \
                   "r"((b)[0]), "r"((b)[1]))

// ---------------------------------------------------------------------------
// device scratch
// ---------------------------------------------------------------------------
__device__ __align__(256) __half g_W[4096 * KTOT];
__device__ __align__(256) __half g_x[(size_t)T_STEPS * MPAD * INPUTD];
__device__ __align__(256) __half g_h[2][MPAD * HID];
__device__ __align__(16) float g_bias[4 * HID];

// decoder fp16 weights
__device__ __align__(256) __half g_attnWh[WW * HID];
__device__ __align__(256) __half g_combWh[HID * HID];
__device__ __align__(256) __half g_gWih16[3 * HID * HID];
__device__ __align__(256) __half g_gWhh16[3 * HID * HID];
__device__ __align__(256) __half g_ctxT[(size_t)HID * WW];

__device__ __align__(16) float g_u[OUTD];
__device__ __align__(16) float g_hdecB[2][HID];    // double-buffered GRU state
__device__ __align__(16) float g_comb[HID];
__device__ __align__(16) float g_v2[HID + OUTD];   // [u; applied]
__device__ float g_sch[WW];

__device__ unsigned g_bcnt = 0;
__device__ volatile unsigned g_bgen = 0;
__device__ unsigned g_bcH[2] = {0, 0};
__device__ volatile unsigned g_bgH[2] = {0, 0};

__device__ __forceinline__ void gbar(unsigned nctas) {
    __syncthreads();
    if (threadIdx.x == 0) {
        __threadfence();
        unsigned gen = g_bgen;
        if (atomicAdd(&g_bcnt, 1u) == nctas - 1u) {
            g_bcnt = 0;
            __threadfence();
            g_bgen = gen + 1u;
        } else {
            while (g_bgen == gen) __nanosleep(32);
        }
        __threadfence();
    }
    __syncthreads();
}

__device__ __forceinline__ void gbarH(int h, unsigned nctas) {
    __syncthreads();
    if (threadIdx.x == 0) {
        __threadfence();
        unsigned gen = g_bgH[h];
        if (atomicAdd(&g_bcH[h], 1u) == nctas - 1u) {
            g_bcH[h] = 0;
            __threadfence();
            g_bgH[h] = gen + 1u;
        } else {
            while (g_bgH[h] == gen) __nanosleep(32);
        }
        __threadfence();
    }
    __syncthreads();
}

__device__ __forceinline__ float sigf(float x)  { return __fdividef(1.f, 1.f + __expf(-x)); }
__device__ __forceinline__ float tanhf_fast(float x) { return 1.f - __fdividef(2.f, __expf(2.f * x) + 1.f); }
__device__ __forceinline__ float warp_red(float s) {
#pragma unroll
    for (int o = 16; o; o >>= 1) s += __shfl_down_sync(0xffffffffu, s, o);
    return s;
}

// fp16-weight x fp32-vector dot, length 1024, lane-strided
__device__ __forceinline__ float dot1024(const __half* __restrict__ w,
                                         const float* __restrict__ v, int lane) {
    float s = 0.f;
    const uint4* w4 = (const uint4*)w;
#pragma unroll
    for (int k = lane; k < 128; k += 32) {
        uint4 u = w4[k];
        const float4* vv = (const float4*)(v + (k << 3));
        float4 va = vv[0], vb = vv[1];
        float2 f0 = __half22float2(*(__half2*)&u.x);
        float2 f1 = __half22float2(*(__half2*)&u.y);
        float2 f2 = __half22float2(*(__half2*)&u.z);
        float2 f3 = __half22float2(*(__half2*)&u.w);
        s += f0.x * va.x + f0.y * va.y + f1.x * va.z + f1.y * va.w
           + f2.x * vb.x + f2.y * vb.y + f3.x * vb.z + f3.y * vb.w;
    }
    return s;
}

// ---------------------------------------------------------------------------
// fragment machinery (32m x 32n warp tile, single-pass fp16)
// ---------------------------------------------------------------------------
struct Frag {
    uint32_t ah[2][4], bh[4][2];
};

__device__ __forceinline__ void load_frags(Frag& f, uint32_t Ah, uint32_t Bh,
                                           int ks, int wr, int wc, int lane) {
#pragma unroll
    for (int mt = 0; mt < 2; mt++) {
        int r = wr * 32 + mt * 16 + (lane & 15);
        uint32_t ch = ((uint32_t)((ks * 2 + (lane >> 4)) ^ (r & 7))) << 4;
        LDSM4(f.ah[mt], Ah + r * 128 + ch);
    }
#pragma unroll
    for (int gp = 0; gp < 2; gp++) {
        int rn = (gp * 2 + (lane >> 4)) * 16 + wc * 8 + (lane & 7);
        uint32_t ch = ((uint32_t)((ks * 2 + ((lane >> 3) & 1)) ^ (rn & 7))) << 4;
        LDSM4(&f.bh[gp * 2][0], Bh + rn * 128 + ch);
    }
}

__device__ __forceinline__ void do_mmas(float (&acc)[2][4][4], const Frag& f) {
#pragma unroll
    for (int mt = 0; mt < 2; mt++)
#pragma unroll
        for (int q = 0; q < 4; q++)
            MMA16816(acc[mt][q], f.ah[mt], f.bh[q]);
}

// ---------------------------------------------------------------------------
// init / convert
// ---------------------------------------------------------------------------
__global__ void k_init(const float* __restrict__ bih, const float* __restrict__ bhh) {
    int i = blockIdx.x * blockDim.x + threadIdx.x;
    int n = MPAD * HID;
    __half z = __float2half(0.f);
    for (int j = i; j < n; j += gridDim.x * blockDim.x) {
        g_h[0][j] = z; g_h[1][j] = z;
    }
    if (i < 4 * HID) g_bias[i] = bih[i] + bhh[i];
}

__global__ void k_conv_w(const float* __restrict__ Whh, const float* __restrict__ Wih) {
    size_t i = (size_t)blockIdx.x * blockDim.x + threadIdx.x;
    if (i >= (size_t)4096 * KTOT) return;
    int r = (int)(i / KTOT);
    int k = (int)(i % KTOT);
    float v = (k < HID) ? Whh[(size_t)r * HID + k] : Wih[(size_t)r * INPUTD + (k - HID)];
    g_W[i] = __float2half(v);
}

__global__ void k_conv_x(const float* __restrict__ data) {
    size_t i = (size_t)blockIdx.x * blockDim.x + threadIdx.x;
    if (i >= (size_t)T_STEPS * MPAD * INPUTD) return;
    int k = (int)(i % INPUTD);
    int b = (int)((i / INPUTD) % MPAD);
    int t = (int)(i / ((size_t)MPAD * INPUTD));
    float v = (b < BATCH) ? data[((size_t)t * BATCH + b) * INPUTD + k] : 0.f;
    g_x[i] = __float2half(v);
}

__global__ void k_conv_dec(const float* __restrict__ attn_W, const float* __restrict__ comb_W,
                           const float* __restrict__ gWih, const float* __restrict__ gWhh) {
    size_t i = (size_t)blockIdx.x * blockDim.x + threadIdx.x;
    const size_t nA = (size_t)WW * HID;
    const size_t nC = (size_t)HID * HID;
    const size_t nG = (size_t)3 * HID * HID;
    if (i < nA) {
        size_t j = i / HID, k = i % HID;
        g_attnWh[i] = __float2half(attn_W[j * (HID + OUTD) + OUTD + k]);
        return;
    }
    i -= nA;
    if (i < nC) {
        size_t r = i / HID, k = i % HID;
        g_combWh[i] = __float2half(comb_W[r * (HID + OUTD) + OUTD + k]);
        return;
    }
    i -= nC;
    if (i < nG) { g_gWih16[i] = __float2half(gWih[i]); return; }
    i -= nG;
    if (i < nG) { g_gWhh16[i] = __float2half(gWhh[i]); return; }
}

// ---------------------------------------------------------------------------
// k_enc: persistent, 240 LSTM steps, weights resident (160KB), c in registers.
// K=128 chunks (two stacked K64 subtiles), 2x32KB A ring, 10 syncs/step.
// 128 CTAs x 256 thr; per-m-half barrier (64 CTAs each).
// ---------------------------------------------------------------------------
__global__ __launch_bounds__(256, 1) void k_enc() {
    extern __shared__ __align__(128) char smem[];
    const uint32_t sb  = smem_to_u32(smem);
    const uint32_t sbW = sb;
    const uint32_t sbA = sb + SMW;
    const int tid  = threadIdx.x;
    const int lane = tid & 31;
    const int wid  = tid >> 5;
    const int wr   = wid & 3;
    const int wc   = wid >> 2;
    const int n0   = (blockIdx.x & 63) * 16;
    const int mh   = blockIdx.x >> 6;
    const int m0   = mh * 128;
    const int rowq = lane >> 2;
    const int col2 = (lane & 3) * 2;

    // resident W: 20 K64 tiles x 8KB (contiguous => K128 chunk ci at ci*16384)
    for (int i = tid; i < 10240; i += 256) {
        int ci = i >> 9, r = (i >> 3) & 63, ch = i & 7;
        int wrow = (r >> 4) * HID + n0 + (r & 15);
        size_t off = (size_t)wrow * KTOT + ci * 64 + ch * 8;
        uint32_t dst = sbW + ci * 8192 + r * 128 + (((uint32_t)(ch ^ (r & 7))) << 4);
        CP_ASYNC16(dst, g_W + off);
    }
    CP_COMMIT();

    int lb = 0, cbuf = 0;

    auto loadX2 = [&](int t, int j) {    // x K128 chunk j (cols j*128..)
        uint32_t base = sbA + lb * 32768; lb ^= 1;
#pragma unroll
        for (int s = 0; s < 2; s++) {
            int k0 = j * 128 + s * 64;
#pragma unroll
            for (int i = tid; i < 1024; i += 256) {
                int r = i >> 3, ch = i & 7;
                size_t off = ((size_t)t * MPAD + m0 + r) * INPUTD + k0 + ch * 8;
                CP_ASYNC16(base + s * 16384 + r * 128 + (((uint32_t)(ch ^ (r & 7))) << 4),
                           g_x + off);
            }
        }
        CP_COMMIT();
    };
    auto loadH2 = [&](const __half* hIn, int c) {   // h K128 chunk c
        uint32_t base = sbA + lb * 32768; lb ^= 1;
#pragma unroll
        for (int s = 0; s < 2; s++) {
            int k0 = c * 128 + s * 64;
#pragma unroll
            for (int i = tid; i < 1024; i += 256) {
                int r = i >> 3, ch = i & 7;
                size_t off = (size_t)(m0 + r) * HID + k0 + ch * 8;
                CP_ASYNC16(base + s * 16384 + r * 128 + (((uint32_t)(ch ^ (r & 7))) << 4),
                           hIn + off);
            }
        }
        CP_COMMIT();
    };

    float acc[2][4][4];
    float creg[2][2][2];
#pragma unroll
    for (int a = 0; a < 2; a++)
#pragma unroll
        for (int b = 0; b < 2; b++)
#pragma unroll
            for (int d = 0; d < 2; d++) creg[a][b][d] = 0.f;
#pragma unroll
    for (int mt = 0; mt < 2; mt++)
#pragma unroll
        for (int q = 0; q < 4; q++)
#pragma unroll
            for (int j = 0; j < 4; j++) acc[mt][q][j] = 0.f;

    // compute one K128 chunk: wchunk in 0..9 (0..7 h, 8..9 x)
    auto computeChunk = [&](int wchunk) {
        uint32_t Ab = sbA + cbuf * 32768; cbuf ^= 1;
        uint32_t Bb = sbW + wchunk * 16384;
        Frag fr[2];
        load_frags(fr[0], Ab, Bb, 0, wr, wc, lane);
#pragma unroll
        for (int ks = 0; ks < 8; ks++) {
            if (ks < 7) {
                int kn = ks + 1;
                load_frags(fr[(kn) & 1], Ab + (kn >> 2) * 16384, Bb + (kn >> 2) * 8192,
                           kn & 3, wr, wc, lane);
            }
            do_mmas(acc, fr[ks & 1]);
        }
    };

    // prologue: both x chunks of step 0
    loadX2(0, 0); loadX2(0, 1);

    for (int t = 0; t < T_STEPS; t++) {
        const __half* __restrict__ hIn = g_h[t & 1];

        // x chunk 0 (pre-barrier)
        CP_WAIT1(); __syncthreads(); computeChunk(8);

        gbarH(mh, 64);   // h(t) now visible

        loadH2(hIn, 0);
        // x chunk 1 (overlaps loadH0)
        CP_WAIT1(); __syncthreads(); computeChunk(9);
        loadH2(hIn, 1);

        // h phase: 8 K128 chunks
        for (int c = 0; c < 8; c++) {
            if (t == T_STEPS - 1 && c == 7) { CP_WAIT0(); } else { CP_WAIT1(); }
            __syncthreads();
            computeChunk(c);
            if (c < 6)                loadH2(hIn, c + 2);
            else if (t + 1 < T_STEPS) loadX2(t + 1, c - 6);
        }

        // fused LSTM gate epilogue (c in registers)
        __half* __restrict__ hOut = g_h[(t + 1) & 1];
#pragma unroll
        for (int mt = 0; mt < 2; mt++)
#pragma unroll
            for (int rp = 0; rp < 2; rp++) {
                int m = m0 + wr * 32 + mt * 16 + rowq + rp * 8;
                if (m < BATCH) {
                    int n = n0 + wc * 8 + col2;
                    size_t idx = (size_t)m * HID + n;
                    float2 bi = *(const float2*)&g_bias[n];
                    float2 bf = *(const float2*)&g_bias[HID + n];
                    float2 bg = *(const float2*)&g_bias[2 * HID + n];
                    float2 bo = *(const float2*)&g_bias[3 * HID + n];
                    float h[2];
#pragma unroll
                    for (int j = 0; j < 2; j++) {
                        float gi = acc[mt][0][rp * 2 + j] + (j ? bi.y : bi.x);
                        float gf = acc[mt][1][rp * 2 + j] + (j ? bf.y : bf.x);
                        float gg = acc[mt][2][rp * 2 + j] + (j ? bg.y : bg.x);
                        float go = acc[mt][3][rp * 2 + j] + (j ? bo.y : bo.x);
                        float cn = sigf(gf) * creg[mt][rp][j] + sigf(gi) * tanhf_fast(gg);
                        creg[mt][rp][j] = cn;
                        h[j] = sigf(go) * tanhf_fast(cn);
                    }
                    *(__half2*)&hOut[idx] =
                        __halves2half2(__float2half(h[0]), __float2half(h[1]));
                }
            }

        // reset accumulators
#pragma unroll
        for (int mt = 0; mt < 2; mt++)
#pragma unroll
            for (int q = 0; q < 4; q++)
#pragma unroll
                for (int j = 0; j < 4; j++) acc[mt][q][j] = 0.f;
    }
}

// ---------------------------------------------------------------------------
// k_dec: persistent decoder, 64 CTAs x 256 thr, 4 barriers/step.
// GRU rows CTA-local (smem), hdec double-buffered.
// ---------------------------------------------------------------------------
__global__ __launch_bounds__(256, 1) void k_dec(
    const float* __restrict__ attn_W, const float* __restrict__ attn_b,
    const float* __restrict__ comb_W, const float* __restrict__ comb_b,
    const float* __restrict__ gbih,   const float* __restrict__ gbhh,
    const float* __restrict__ out_W,  const float* __restrict__ out_b,
    float* __restrict__ outp)
{
    __shared__ float s_aw[WW];
    __shared__ float rbuf[8];
    __shared__ float lg[OUTD];
    __shared__ float s_g[96];   // CTA-local gi(48) + gh(48)

    const int tid  = threadIdx.x;
    const int bid  = blockIdx.x;
    const int lane = tid & 31;
    const int warp = tid >> 5;
    const int gw   = bid * 8 + warp;   // 0..511
    const int gt   = bid * 256 + tid;  // 0..16383

    // init: hdec buffer 0, u, transposed ctx
    if (gt < HID) g_hdecB[0][gt] = __half2float(g_h[0][(size_t)(BATCH - 1) * HID + gt]);
    if (gt < OUTD) g_u[gt] = 0.125f;
    for (size_t i = gt; i < (size_t)WW * HID; i += NCTA_D * 256) {
        size_t j = i / HID, n = i % HID;
        g_ctxT[n * WW + j] = g_h[0][j * HID + n];
    }
    gbar(NCTA_D);

    auto out_head = [&](int sidx, const float* hv) {
        if (warp < OUTD) {
            const float4* row = (const float4*)(out_W + (size_t)warp * HID);
            const float4* v   = (const float4*)hv;
            float s = 0.f;
            for (int k = lane; k < HID / 4; k += 32) {
                float4 w = row[k], x = v[k];
                s += w.x * x.x + w.y * x.y + w.z * x.z + w.w * x.w;
            }
            s = warp_red(s);
            if (!lane) lg[warp] = s + out_b[warp];
        }
        __syncthreads();
        if (tid == 0) {
            float mx = -1e30f;
#pragma unroll
            for (int i = 0; i < OUTD; i++) mx = fmaxf(mx, lg[i]);
            float sum = 0.f;
#pragma unroll
            for (int i = 0; i < OUTD; i++) sum += __expf(lg[i] - mx);
            float lse = mx + __logf(sum);
#pragma unroll
            for (int i = 0; i < OUTD; i++) {
                float lp = lg[i] - lse;
                outp[sidx * OUTD + i] = lp;
                g_u[i] = lp;
            }
        }
        __syncthreads();
    };

    for (int s = 0; s < NSTEPS; s++) {
        const float* __restrict__ hcur = g_hdecB[s & 1];
        float* __restrict__ hnxt       = g_hdecB[(s + 1) & 1];

        // P1: CTA0 -> prev-step output head (writes u); others -> attn score_h
        if (bid == 0) {
            if (s > 0) out_head(s - 1, hcur);
        } else {
            int j = gw - 8;
            if (j < WW) {
                float x = dot1024(g_attnWh + (size_t)j * HID, hcur, lane);
                x = warp_red(x);
                if (!lane) g_sch[j] = x;
            }
        }
        gbar(NCTA_D);

        // P2: per-CTA redundant softmax + applied columns
        {
            float x;
            if (tid < WW) {
                float su = 0.f;
#pragma unroll
                for (int k = 0; k < OUTD; k++)
                    su += g_u[k] * attn_W[(size_t)tid * (HID + OUTD) + k];
                x = g_sch[tid] + su + attn_b[tid];
            } else x = -1e30f;
            float mx = x;
#pragma unroll
            for (int o = 16; o; o >>= 1) mx = fmaxf(mx, __shfl_xor_sync(0xffffffffu, mx, o));
            if (!lane) rbuf[warp] = mx;
            __syncthreads();
            float bm = rbuf[0];
#pragma unroll
            for (int i = 1; i < 8; i++) bm = fmaxf(bm, rbuf[i]);
            float e = (tid < WW) ? __expf(x - bm) : 0.f;
            float sm = e;
#pragma unroll
            for (int o = 16; o; o >>= 1) sm += __shfl_xor_sync(0xffffffffu, sm, o);
            __syncthreads();
            if (!lane) rbuf[warp] = sm;
            __syncthreads();
            float tot = 0.f;
#pragma unroll
            for (int i = 0; i < 8; i++) tot += rbuf[i];
            if (tid < WW) s_aw[tid] = e / tot;
            __syncthreads();
#pragma unroll
            for (int rep = 0; rep < 2; rep++) {
                int n = bid * 8 + warp + rep * 512;
                const __half* ct = g_ctxT + (size_t)n * WW;
                float a = 0.f;
                for (int j = lane; j < WW; j += 32) a += s_aw[j] * __half2float(ct[j]);
                a = warp_red(a);
                if (!lane) g_v2[OUTD + n] = a;
            }
            if (bid == 0 && tid < OUTD) g_v2[tid] = g_u[tid];
        }
        gbar(NCTA_D);

        // P3: comb = relu(comb_W @ [u; applied] + b)
#pragma unroll
        for (int rep = 0; rep < 2; rep++) {
            int r = gw + rep * 512;
            float x = dot1024(g_combWh + (size_t)r * HID, g_v2 + OUTD, lane);
            x = warp_red(x);
            if (!lane) {
                float su = 0.f;
#pragma unroll
                for (int k = 0; k < OUTD; k++)
                    su += comb_W[(size_t)r * (HID + OUTD) + k] * g_v2[k];
                g_comb[r] = fmaxf(x + su + comb_b[r], 0.f);
            }
        }
        gbar(NCTA_D);

        // P4+P5 fused: this CTA's 96 GRU rows (3 gi + 3 gh gates x 16) -> smem,
        // then update this CTA's 16 hdec entries into the NEXT buffer.
        for (int idx = warp; idx < 96; idx += 8) {
            int p = idx >> 4, i = idx & 15;
            int n = bid * 16 + i;
            float x;
            if (p < 3) x = dot1024(g_gWih16 + ((size_t)p * HID + n) * HID, g_comb, lane);
            else       x = dot1024(g_gWhh16 + ((size_t)(p - 3) * HID + n) * HID, hcur, lane);
            x = warp_red(x);
            if (!lane) {
                if (p < 3) s_g[idx] = x + gbih[p * HID + n];
                else       s_g[idx] = x + gbhh[(p - 3) * HID + n];
            }
        }
        __syncthreads();
        if (tid < 16) {
            int n = bid * 16 + tid;
            float r  = sigf(s_g[tid] + s_g[48 + tid]);
            float z  = sigf(s_g[16 + tid] + s_g[64 + tid]);
            float nn = tanhf_fast(s_g[32 + tid] + r * s_g[80 + tid]);
            hnxt[n] = (1.f - z) * nn + z * hcur[n];
        }
        gbar(NCTA_D);
    }

    // final output head (state after step NSTEPS-1 lives in buffer NSTEPS&1)
    if (bid == 0) out_head(NSTEPS - 1, g_hdecB[NSTEPS & 1]);
}

// ---------------------------------------------------------------------------
// launch
// ---------------------------------------------------------------------------
extern "C" void kernel_launch(void* const* d_in, const int* in_sizes, int n_in,
                              void* d_out, int out_size) {
    const float* data     = (const float*)d_in[0];
    const float* enc_Wih  = (const float*)d_in[1];
    const float* enc_Whh  = (const float*)d_in[2];
    const float* enc_bih  = (const float*)d_in[3];
    const float* enc_bhh  = (const float*)d_in[4];
    const float* attn_W   = (const float*)d_in[5];
    const float* attn_b   = (const float*)d_in[6];
    const float* comb_W   = (const float*)d_in[7];
    const float* comb_b   = (const float*)d_in[8];
    const float* gru_Wih  = (const float*)d_in[9];
    const float* gru_Whh  = (const float*)d_in[10];
    const float* gru_bih  = (const float*)d_in[11];
    const float* gru_bhh  = (const float*)d_in[12];
    const float* out_W    = (const float*)d_in[13];
    const float* out_b    = (const float*)d_in[14];
    float* out = (float*)d_out;

    cudaFuncSetAttribute(k_enc, cudaFuncAttributeMaxDynamicSharedMemorySize, SMEMB);

    k_init<<<1024, 256>>>(enc_bih, enc_bhh);
    k_conv_w<<<(4096 * KTOT + 255) / 256, 256>>>(enc_Whh, enc_Wih);
    k_conv_x<<<(T_STEPS * MPAD * INPUTD + 255) / 256, 256>>>(data);
    {
        size_t ntot = (size_t)WW * HID + (size_t)HID * HID + 2 * (size_t)3 * HID * HID;
        k_conv_dec<<<(int)((ntot + 255) / 256), 256>>>(attn_W, comb_W, gru_Wih, gru_Whh);
    }

    k_enc<<<NCTA, 256, SMEMB>>>();

    k_dec<<<NCTA_D, 256>>>(attn_W, attn_b, comb_W, comb_b,
                           gru_bih, gru_bhh, out_W, out_b, out);
}

// round 14
// speedup vs baseline: 1.7385x; 1.0834x over previous
#include <cuda_runtime.h>
#include <cuda_fp16.h>
#include <math.h>
#include <cstdint>

#define T_STEPS 240
#define BATCH   240
#define MPAD    256
#define INPUTD  256
#define HID     1024
#define NSTEPS  30
#define OUTD    8
#define WW      240
#define KTOT    1280
#define NCTA    128
#define NCTA_D  64

// encoder smem: W resident 160KB + A ring 2 x 32KB = 224KB
#define SMW     163840
#define SMEMB   (SMW + 2 * 32768)

// ---------------------------------------------------------------------------
// helpers
// ---------------------------------------------------------------------------
__device__ __forceinline__ uint32_t smem_to_u32(const void* p) {
    uint32_t a;
    asm("{ .reg .u64 t; cvta.to.shared.u64 t, %1; cvt.u32.u64 %0, t; }" : "=r"(a) : "l"(p));
    return a;
}

#define CP_ASYNC16(dst, src) \
    asm volatile("cp.async.cg.shared.global [%0], [%1], 16;" \
                 :: "r"(dst), "l"(__cvta_generic_to_global(src)))
#define CP_COMMIT() asm volatile("cp.async.commit_group;" ::: "memory")
#define CP_WAIT1()  asm volatile("cp.async.wait_group 1;" ::: "memory")
#define CP_WAIT0()  asm volatile("cp.async.wait_group 0;" ::: "memory")

#define LDSM4(r, addr) \
    asm volatile("ldmatrix.sync.aligned.m8n8.x4.shared.b16 {%0,%1,%2,%3}, [%4];" \
                 : "=r"((r)[0]), "=r"((r)[1]), "=r"((r)[2]), "=r"((r)[3]) : "r"(addr))

#define MMA16816(d, a, b) \
    asm volatile("mma.sync.aligned.m16n8k16.row.col.f32.f16.f16.f32 " \
                 "{%0,%1,%2,%3}, {%4,%5,%6,%7}, {%8,%9}, {%0,%1,%2,%3};" \
                 : "+f"((d)[0]), "+f"((d)[1]), "+f"((d)[2]), "+f"((d)[3]) \
                 : "r"((a)[0]), "r"((a)[1]), "r"((a)[2]), "r"((a)[3]), \
                   "r"((b)[0]), "r"((b)[1]))

// ---------------------------------------------------------------------------
// device scratch
// ---------------------------------------------------------------------------
__device__ __align__(256) __half g_W[4096 * KTOT];
__device__ __align__(256) __half g_x[(size_t)T_STEPS * MPAD * INPUTD];
__device__ __align__(256) __half g_h[2][MPAD * HID];
__device__ __align__(16) float g_bias[4 * HID];

// decoder fp16 weights
__device__ __align__(256) __half g_attnWh[WW * HID];
__device__ __align__(256) __half g_combWh[HID * HID];
__device__ __align__(256) __half g_gWih16[3 * HID * HID];
__device__ __align__(256) __half g_gWhh16[3 * HID * HID];
__device__ __align__(256) __half g_ctxT[(size_t)HID * WW];

__device__ __align__(16) float g_u[OUTD];
__device__ __align__(16) float g_hdecB[2][HID];    // double-buffered GRU state
__device__ __align__(16) float g_comb[HID];
__device__ __align__(16) float g_v2[HID + OUTD];   // [u; applied]
__device__ float g_sch[WW];

__device__ unsigned g_bcnt = 0;
__device__ volatile unsigned g_bgen = 0;
__device__ unsigned g_bcH[2] = {0, 0};
__device__ volatile unsigned g_bgH[2] = {0, 0};

__device__ __forceinline__ void gbar(unsigned nctas) {
    __syncthreads();
    if (threadIdx.x == 0) {
        __threadfence();
        unsigned gen = g_bgen;
        if (atomicAdd(&g_bcnt, 1u) == nctas - 1u) {
            g_bcnt = 0;
            __threadfence();
            g_bgen = gen + 1u;
        } else {
            while (g_bgen == gen) __nanosleep(32);
        }
        __threadfence();
    }
    __syncthreads();
}

__device__ __forceinline__ float sigf(float x)  { return __fdividef(1.f, 1.f + __expf(-x)); }
__device__ __forceinline__ float tanhf_fast(float x) { return 1.f - __fdividef(2.f, __expf(2.f * x) + 1.f); }
__device__ __forceinline__ float warp_red(float s) {
#pragma unroll
    for (int o = 16; o; o >>= 1) s += __shfl_down_sync(0xffffffffu, s, o);
    return s;
}

// fp16-weight x fp32-vector dot, length 1024, lane-strided
__device__ __forceinline__ float dot1024(const __half* __restrict__ w,
                                         const float* __restrict__ v, int lane) {
    float s = 0.f;
    const uint4* w4 = (const uint4*)w;
#pragma unroll
    for (int k = lane; k < 128; k += 32) {
        uint4 u = w4[k];
        const float4* vv = (const float4*)(v + (k << 3));
        float4 va = vv[0], vb = vv[1];
        float2 f0 = __half22float2(*(__half2*)&u.x);
        float2 f1 = __half22float2(*(__half2*)&u.y);
        float2 f2 = __half22float2(*(__half2*)&u.z);
        float2 f3 = __half22float2(*(__half2*)&u.w);
        s += f0.x * va.x + f0.y * va.y + f1.x * va.z + f1.y * va.w
           + f2.x * vb.x + f2.y * vb.y + f3.x * vb.z + f3.y * vb.w;
    }
    return s;
}

// ---------------------------------------------------------------------------
// fragment machinery (32m x 32n warp tile, single-pass fp16)
// ---------------------------------------------------------------------------
struct Frag {
    uint32_t ah[2][4], bh[4][2];
};

__device__ __forceinline__ void load_frags(Frag& f, uint32_t Ah, uint32_t Bh,
                                           int ks, int wr, int wc, int lane) {
#pragma unroll
    for (int mt = 0; mt < 2; mt++) {
        int r = wr * 32 + mt * 16 + (lane & 15);
        uint32_t ch = ((uint32_t)((ks * 2 + (lane >> 4)) ^ (r & 7))) << 4;
        LDSM4(f.ah[mt], Ah + r * 128 + ch);
    }
#pragma unroll
    for (int gp = 0; gp < 2; gp++) {
        int rn = (gp * 2 + (lane >> 4)) * 16 + wc * 8 + (lane & 7);
        uint32_t ch = ((uint32_t)((ks * 2 + ((lane >> 3) & 1)) ^ (rn & 7))) << 4;
        LDSM4(&f.bh[gp * 2][0], Bh + rn * 128 + ch);
    }
}

__device__ __forceinline__ void do_mmas(float (&acc)[2][4][4], const Frag& f) {
#pragma unroll
    for (int mt = 0; mt < 2; mt++)
#pragma unroll
        for (int q = 0; q < 4; q++)
            MMA16816(acc[mt][q], f.ah[mt], f.bh[q]);
}

// ---------------------------------------------------------------------------
// init / convert
// ---------------------------------------------------------------------------
__global__ void k_init(const float* __restrict__ bih, const float* __restrict__ bhh) {
    int i = blockIdx.x * blockDim.x + threadIdx.x;
    int n = MPAD * HID;
    __half z = __float2half(0.f);
    for (int j = i; j < n; j += gridDim.x * blockDim.x) {
        g_h[0][j] = z; g_h[1][j] = z;
    }
    if (i < 4 * HID) g_bias[i] = bih[i] + bhh[i];
    if (i < 2) { g_bcH[i] = 0; g_bgH[i] = 0; }   // reset barrier state (graph replay)
    if (i == 2) { g_bcnt = 0; g_bgen = 0; }
}

__global__ void k_conv_w(const float* __restrict__ Whh, const float* __restrict__ Wih) {
    size_t i = (size_t)blockIdx.x * blockDim.x + threadIdx.x;
    if (i >= (size_t)4096 * KTOT) return;
    int r = (int)(i / KTOT);
    int k = (int)(i % KTOT);
    float v = (k < HID) ? Whh[(size_t)r * HID + k] : Wih[(size_t)r * INPUTD + (k - HID)];
    g_W[i] = __float2half(v);
}

__global__ void k_conv_x(const float* __restrict__ data) {
    size_t i = (size_t)blockIdx.x * blockDim.x + threadIdx.x;
    if (i >= (size_t)T_STEPS * MPAD * INPUTD) return;
    int k = (int)(i % INPUTD);
    int b = (int)((i / INPUTD) % MPAD);
    int t = (int)(i / ((size_t)MPAD * INPUTD));
    float v = (b < BATCH) ? data[((size_t)t * BATCH + b) * INPUTD + k] : 0.f;
    g_x[i] = __float2half(v);
}

__global__ void k_conv_dec(const float* __restrict__ attn_W, const float* __restrict__ comb_W,
                           const float* __restrict__ gWih, const float* __restrict__ gWhh) {
    size_t i = (size_t)blockIdx.x * blockDim.x + threadIdx.x;
    const size_t nA = (size_t)WW * HID;
    const size_t nC = (size_t)HID * HID;
    const size_t nG = (size_t)3 * HID * HID;
    if (i < nA) {
        size_t j = i / HID, k = i % HID;
        g_attnWh[i] = __float2half(attn_W[j * (HID + OUTD) + OUTD + k]);
        return;
    }
    i -= nA;
    if (i < nC) {
        size_t r = i / HID, k = i % HID;
        g_combWh[i] = __float2half(comb_W[r * (HID + OUTD) + OUTD + k]);
        return;
    }
    i -= nC;
    if (i < nG) { g_gWih16[i] = __float2half(gWih[i]); return; }
    i -= nG;
    if (i < nG) { g_gWhh16[i] = __float2half(gWhh[i]); return; }
}

// ---------------------------------------------------------------------------
// k_enc: persistent, 240 LSTM steps, weights resident (160KB), c in registers.
// Split-phase barrier: arrive after epilogue -> compute x chunk (barrier
// latency hidden) -> wait -> h phase.
// ---------------------------------------------------------------------------
__global__ __launch_bounds__(256, 1) void k_enc() {
    extern __shared__ __align__(128) char smem[];
    const uint32_t sb  = smem_to_u32(smem);
    const uint32_t sbW = sb;
    const uint32_t sbA = sb + SMW;
    const int tid  = threadIdx.x;
    const int lane = tid & 31;
    const int wid  = tid >> 5;
    const int wr   = wid & 3;
    const int wc   = wid >> 2;
    const int n0   = (blockIdx.x & 63) * 16;
    const int mh   = blockIdx.x >> 6;
    const int m0   = mh * 128;
    const int rowq = lane >> 2;
    const int col2 = (lane & 3) * 2;

    // resident W: 20 K64 tiles x 8KB (K128 chunk ci at ci*16384)
    for (int i = tid; i < 10240; i += 256) {
        int ci = i >> 9, r = (i >> 3) & 63, ch = i & 7;
        int wrow = (r >> 4) * HID + n0 + (r & 15);
        size_t off = (size_t)wrow * KTOT + ci * 64 + ch * 8;
        uint32_t dst = sbW + ci * 8192 + r * 128 + (((uint32_t)(ch ^ (r & 7))) << 4);
        CP_ASYNC16(dst, g_W + off);
    }
    CP_COMMIT();

    int lb = 0, cbuf = 0;

    auto loadX2 = [&](int t, int j) {
        uint32_t base = sbA + lb * 32768; lb ^= 1;
#pragma unroll
        for (int s = 0; s < 2; s++) {
            int k0 = j * 128 + s * 64;
#pragma unroll
            for (int i = tid; i < 1024; i += 256) {
                int r = i >> 3, ch = i & 7;
                size_t off = ((size_t)t * MPAD + m0 + r) * INPUTD + k0 + ch * 8;
                CP_ASYNC16(base + s * 16384 + r * 128 + (((uint32_t)(ch ^ (r & 7))) << 4),
                           g_x + off);
            }
        }
        CP_COMMIT();
    };
    auto loadH2 = [&](const __half* hIn, int c) {
        uint32_t base = sbA + lb * 32768; lb ^= 1;
#pragma unroll
        for (int s = 0; s < 2; s++) {
            int k0 = c * 128 + s * 64;
#pragma unroll
            for (int i = tid; i < 1024; i += 256) {
                int r = i >> 3, ch = i & 7;
                size_t off = (size_t)(m0 + r) * HID + k0 + ch * 8;
                CP_ASYNC16(base + s * 16384 + r * 128 + (((uint32_t)(ch ^ (r & 7))) << 4),
                           hIn + off);
            }
        }
        CP_COMMIT();
    };

    float acc[2][4][4];
    float creg[2][2][2];
#pragma unroll
    for (int a = 0; a < 2; a++)
#pragma unroll
        for (int b = 0; b < 2; b++)
#pragma unroll
            for (int d = 0; d < 2; d++) creg[a][b][d] = 0.f;
#pragma unroll
    for (int mt = 0; mt < 2; mt++)
#pragma unroll
        for (int q = 0; q < 4; q++)
#pragma unroll
            for (int j = 0; j < 4; j++) acc[mt][q][j] = 0.f;

    auto computeChunk = [&](int wchunk) {
        uint32_t Ab = sbA + cbuf * 32768; cbuf ^= 1;
        uint32_t Bb = sbW + wchunk * 16384;
        Frag fr[2];
        load_frags(fr[0], Ab, Bb, 0, wr, wc, lane);
#pragma unroll
        for (int ks = 0; ks < 8; ks++) {
            if (ks < 7) {
                int kn = ks + 1;
                load_frags(fr[kn & 1], Ab + (kn >> 2) * 16384, Bb + (kn >> 2) * 8192,
                           kn & 3, wr, wc, lane);
            }
            do_mmas(acc, fr[ks & 1]);
        }
    };

    unsigned snap = 0;   // thread0's barrier generation snapshot

    // prologue: x chunks of step 0 (h(0)=0, already initialized; no barrier)
    loadX2(0, 0); loadX2(0, 1);
    CP_WAIT1(); __syncthreads(); computeChunk(8);
    loadH2(g_h[0], 0);
    CP_WAIT1(); __syncthreads(); computeChunk(9);
    loadH2(g_h[0], 1);

    for (int t = 0; t < T_STEPS; t++) {
        const __half* __restrict__ hIn = g_h[t & 1];

        // h phase: 8 K128 chunks
        for (int c = 0; c < 8; c++) {
            if (t == T_STEPS - 1 && c == 7) { CP_WAIT0(); } else { CP_WAIT1(); }
            __syncthreads();
            computeChunk(c);
            if (c < 6)                loadH2(hIn, c + 2);
            else if (t + 1 < T_STEPS) loadX2(t + 1, c - 6);
        }

        // fused LSTM gate epilogue (c in registers)
        __half* __restrict__ hOut = g_h[(t + 1) & 1];
#pragma unroll
        for (int mt = 0; mt < 2; mt++)
#pragma unroll
            for (int rp = 0; rp < 2; rp++) {
                int m = m0 + wr * 32 + mt * 16 + rowq + rp * 8;
                if (m < BATCH) {
                    int n = n0 + wc * 8 + col2;
                    size_t idx = (size_t)m * HID + n;
                    float2 bi = *(const float2*)&g_bias[n];
                    float2 bf = *(const float2*)&g_bias[HID + n];
                    float2 bg = *(const float2*)&g_bias[2 * HID + n];
                    float2 bo = *(const float2*)&g_bias[3 * HID + n];
                    float h[2];
#pragma unroll
                    for (int j = 0; j < 2; j++) {
                        float gi = acc[mt][0][rp * 2 + j] + (j ? bi.y : bi.x);
                        float gf = acc[mt][1][rp * 2 + j] + (j ? bf.y : bf.x);
                        float gg = acc[mt][2][rp * 2 + j] + (j ? bg.y : bg.x);
                        float go = acc[mt][3][rp * 2 + j] + (j ? bo.y : bo.x);
                        float cn = sigf(gf) * creg[mt][rp][j] + sigf(gi) * tanhf_fast(gg);
                        creg[mt][rp][j] = cn;
                        h[j] = sigf(go) * tanhf_fast(cn);
                    }
                    *(__half2*)&hOut[idx] =
                        __halves2half2(__float2half(h[0]), __float2half(h[1]));
                }
            }

        if (t + 1 == T_STEPS) break;

        // ---- ARRIVE (publish h(t+1)) ----
        __threadfence();
        __syncthreads();
        if (tid == 0) {
            snap = g_bgH[mh];
            if (atomicAdd(&g_bcH[mh], 1u) == 63u) {
                g_bcH[mh] = 0;
                __threadfence();
                g_bgH[mh] = snap + 1u;
            }
        }

        // reset accumulators, then x chunk 8 of t+1 (hides barrier latency)
#pragma unroll
        for (int mt = 0; mt < 2; mt++)
#pragma unroll
            for (int q = 0; q < 4; q++)
#pragma unroll
                for (int j = 0; j < 4; j++) acc[mt][q][j] = 0.f;

        CP_WAIT1(); __syncthreads(); computeChunk(8);

        // ---- WAIT (h(t+1) visible everywhere) ----
        if (tid == 0) {
            while (g_bgH[mh] == snap) __nanosleep(32);
            __threadfence();
        }
        __syncthreads();

        const __half* __restrict__ hN = g_h[(t + 1) & 1];
        loadH2(hN, 0);
        CP_WAIT1(); __syncthreads(); computeChunk(9);   // hides loadH0 latency
        loadH2(hN, 1);
    }
}

// ---------------------------------------------------------------------------
// k_dec: persistent decoder, 64 CTAs x 256 thr, 4 barriers/step (as R13).
// ---------------------------------------------------------------------------
__global__ __launch_bounds__(256, 1) void k_dec(
    const float* __restrict__ attn_W, const float* __restrict__ attn_b,
    const float* __restrict__ comb_W, const float* __restrict__ comb_b,
    const float* __restrict__ gbih,   const float* __restrict__ gbhh,
    const float* __restrict__ out_W,  const float* __restrict__ out_b,
    float* __restrict__ outp)
{
    __shared__ float s_aw[WW];
    __shared__ float rbuf[8];
    __shared__ float lg[OUTD];
    __shared__ float s_g[96];

    const int tid  = threadIdx.x;
    const int bid  = blockIdx.x;
    const int lane = tid & 31;
    const int warp = tid >> 5;
    const int gw   = bid * 8 + warp;
    const int gt   = bid * 256 + tid;

    if (gt < HID) g_hdecB[0][gt] = __half2float(g_h[0][(size_t)(BATCH - 1) * HID + gt]);
    if (gt < OUTD) g_u[gt] = 0.125f;
    for (size_t i = gt; i < (size_t)WW * HID; i += NCTA_D * 256) {
        size_t j = i / HID, n = i % HID;
        g_ctxT[n * WW + j] = g_h[0][j * HID + n];
    }
    gbar(NCTA_D);

    auto out_head = [&](int sidx, const float* hv) {
        if (warp < OUTD) {
            const float4* row = (const float4*)(out_W + (size_t)warp * HID);
            const float4* v   = (const float4*)hv;
            float s = 0.f;
            for (int k = lane; k < HID / 4; k += 32) {
                float4 w = row[k], x = v[k];
                s += w.x * x.x + w.y * x.y + w.z * x.z + w.w * x.w;
            }
            s = warp_red(s);
            if (!lane) lg[warp] = s + out_b[warp];
        }
        __syncthreads();
        if (tid == 0) {
            float mx = -1e30f;
#pragma unroll
            for (int i = 0; i < OUTD; i++) mx = fmaxf(mx, lg[i]);
            float sum = 0.f;
#pragma unroll
            for (int i = 0; i < OUTD; i++) sum += __expf(lg[i] - mx);
            float lse = mx + __logf(sum);
#pragma unroll
            for (int i = 0; i < OUTD; i++) {
                float lp = lg[i] - lse;
                outp[sidx * OUTD + i] = lp;
                g_u[i] = lp;
            }
        }
        __syncthreads();
    };

    for (int s = 0; s < NSTEPS; s++) {
        const float* __restrict__ hcur = g_hdecB[s & 1];
        float* __restrict__ hnxt       = g_hdecB[(s + 1) & 1];

        if (bid == 0) {
            if (s > 0) out_head(s - 1, hcur);
        } else {
            int j = gw - 8;
            if (j < WW) {
                float x = dot1024(g_attnWh + (size_t)j * HID, hcur, lane);
                x = warp_red(x);
                if (!lane) g_sch[j] = x;
            }
        }
        gbar(NCTA_D);

        {
            float x;
            if (tid < WW) {
                float su = 0.f;
#pragma unroll
                for (int k = 0; k < OUTD; k++)
                    su += g_u[k] * attn_W[(size_t)tid * (HID + OUTD) + k];
                x = g_sch[tid] + su + attn_b[tid];
            } else x = -1e30f;
            float mx = x;
#pragma unroll
            for (int o = 16; o; o >>= 1) mx = fmaxf(mx, __shfl_xor_sync(0xffffffffu, mx, o));
            if (!lane) rbuf[warp] = mx;
            __syncthreads();
            float bm = rbuf[0];
#pragma unroll
            for (int i = 1; i < 8; i++) bm = fmaxf(bm, rbuf[i]);
            float e = (tid < WW) ? __expf(x - bm) : 0.f;
            float sm = e;
#pragma unroll
            for (int o = 16; o; o >>= 1) sm += __shfl_xor_sync(0xffffffffu, sm, o);
            __syncthreads();
            if (!lane) rbuf[warp] = sm;
            __syncthreads();
            float tot = 0.f;
#pragma unroll
            for (int i = 0; i < 8; i++) tot += rbuf[i];
            if (tid < WW) s_aw[tid] = e / tot;
            __syncthreads();
#pragma unroll
            for (int rep = 0; rep < 2; rep++) {
                int n = bid * 8 + warp + rep * 512;
                const __half* ct = g_ctxT + (size_t)n * WW;
                float a = 0.f;
                for (int j = lane; j < WW; j += 32) a += s_aw[j] * __half2float(ct[j]);
                a = warp_red(a);
                if (!lane) g_v2[OUTD + n] = a;
            }
            if (bid == 0 && tid < OUTD) g_v2[tid] = g_u[tid];
        }
        gbar(NCTA_D);

#pragma unroll
        for (int rep = 0; rep < 2; rep++) {
            int r = gw + rep * 512;
            float x = dot1024(g_combWh + (size_t)r * HID, g_v2 + OUTD, lane);
            x = warp_red(x);
            if (!lane) {
                float su = 0.f;
#pragma unroll
                for (int k = 0; k < OUTD; k++)
                    su += comb_W[(size_t)r * (HID + OUTD) + k] * g_v2[k];
                g_comb[r] = fmaxf(x + su + comb_b[r], 0.f);
            }
        }
        gbar(NCTA_D);

        for (int idx = warp; idx < 96; idx += 8) {
            int p = idx >> 4, i = idx & 15;
            int n = bid * 16 + i;
            float x;
            if (p < 3) x = dot1024(g_gWih16 + ((size_t)p * HID + n) * HID, g_comb, lane);
            else       x = dot1024(g_gWhh16 + ((size_t)(p - 3) * HID + n) * HID, hcur, lane);
            x = warp_red(x);
            if (!lane) {
                if (p < 3) s_g[idx] = x + gbih[p * HID + n];
                else       s_g[idx] = x + gbhh[(p - 3) * HID + n];
            }
        }
        __syncthreads();
        if (tid < 16) {
            int n = bid * 16 + tid;
            float r  = sigf(s_g[tid] + s_g[48 + tid]);
            float z  = sigf(s_g[16 + tid] + s_g[64 + tid]);
            float nn = tanhf_fast(s_g[32 + tid] + r * s_g[80 + tid]);
            hnxt[n] = (1.f - z) * nn + z * hcur[n];
        }
        gbar(NCTA_D);
    }

    if (bid == 0) out_head(NSTEPS - 1, g_hdecB[NSTEPS & 1]);
}

// ---------------------------------------------------------------------------
// launch
// ---------------------------------------------------------------------------
extern "C" void kernel_launch(void* const* d_in, const int* in_sizes, int n_in,
                              void* d_out, int out_size) {
    const float* data     = (const float*)d_in[0];
    const float* enc_Wih  = (const float*)d_in[1];
    const float* enc_Whh  = (const float*)d_in[2];
    const float* enc_bih  = (const float*)d_in[3];
    const float* enc_bhh  = (const float*)d_in[4];
    const float* attn_W   = (const float*)d_in[5];
    const float* attn_b   = (const float*)d_in[6];
    const float* comb_W   = (const float*)d_in[7];
    const float* comb_b   = (const float*)d_in[8];
    const float* gru_Wih  = (const float*)d_in[9];
    const float* gru_Whh  = (const float*)d_in[10];
    const float* gru_bih  = (const float*)d_in[11];
    const float* gru_bhh  = (const float*)d_in[12];
    const float* out_W    = (const float*)d_in[13];
    const float* out_b    = (const float*)d_in[14];
    float* out = (float*)d_out;

    cudaFuncSetAttribute(k_enc, cudaFuncAttributeMaxDynamicSharedMemorySize, SMEMB);

    k_init<<<1024, 256>>>(enc_bih, enc_bhh);
    k_conv_w<<<(4096 * KTOT + 255) / 256, 256>>>(enc_Whh, enc_Wih);
    k_conv_x<<<(T_STEPS * MPAD * INPUTD + 255) / 256, 256>>>(data);
    {
        size_t ntot = (size_t)WW * HID + (size_t)HID * HID + 2 * (size_t)3 * HID * HID;
        k_conv_dec<<<(int)((ntot + 255) / 256), 256>>>(attn_W, comb_W, gru_Wih, gru_Whh);
    }

    k_enc<<<NCTA, 256, SMEMB>>>();

    k_dec<<<NCTA_D, 256>>>(attn_W, attn_b, comb_W, comb_b,
                           gru_bih, gru_bhh, out_W, out_b, out);
}

// round 15
// speedup vs baseline: 1.8298x; 1.0525x over previous
#include <cuda_runtime.h>
#include <cuda_fp16.h>
#include <math.h>
#include <cstdint>

#define T_STEPS 240
#define BATCH   240
#define MPAD    256
#define INPUTD  256
#define HID     1024
#define NSTEPS  30
#define OUTD    8
#define WW      240
#define KTOT    1280
#define NCTA    128
#define NCTA_D  64

// encoder smem: W resident 160KB + A ring 2 x 32KB = 224KB
#define SMW     163840
#define SMEMB   (SMW + 2 * 32768)

// ---------------------------------------------------------------------------
// helpers
// ---------------------------------------------------------------------------
__device__ __forceinline__ uint32_t smem_to_u32(const void* p) {
    uint32_t a;
    asm("{ .reg .u64 t; cvta.to.shared.u64 t, %1; cvt.u32.u64 %0, t; }" : "=r"(a) : "l"(p));
    return a;
}

#define CP_ASYNC16(dst, src) \
    asm volatile("cp.async.cg.shared.global [%0], [%1], 16;" \
                 :: "r"(dst), "l"(__cvta_generic_to_global(src)))
#define CP_COMMIT() asm volatile("cp.async.commit_group;" ::: "memory")
#define CP_WAIT1()  asm volatile("cp.async.wait_group 1;" ::: "memory")
#define CP_WAIT0()  asm volatile("cp.async.wait_group 0;" ::: "memory")

#define LDSM4(r, addr) \
    asm volatile("ldmatrix.sync.aligned.m8n8.x4.shared.b16 {%0,%1,%2,%3}, [%4];" \
                 : "=r"((r)[0]), "=r"((r)[1]), "=r"((r)[2]), "=r"((r)[3]) : "r"(addr))

#define MMA16816(d, a, b) \
    asm volatile("mma.sync.aligned.m16n8k16.row.col.f32.f16.f16.f32 " \
                 "{%0,%1,%2,%3}, {%4,%5,%6,%7}, {%8,%9}, {%0,%1,%2,%3};" \
                 : "+f"((d)[0]), "+f"((d)[1]), "+f"((d)[2]), "+f"((d)[3]) \
                 : "r"((a)[0]), "r"((a)[1]), "r"((a)[2]), "r"((a)[3]), \
                   "r"((b)[0]), "r"((b)[1]))

// ---------------------------------------------------------------------------
// device scratch
// ---------------------------------------------------------------------------
__device__ __align__(256) __half g_W[4096 * KTOT];
__device__ __align__(256) __half g_x[(size_t)T_STEPS * MPAD * INPUTD];
__device__ __align__(256) __half g_h[2][MPAD * HID];
__device__ __align__(16) float g_bias[4 * HID];

// decoder fp16 weights
__device__ __align__(256) __half g_attnWh[WW * HID];
__device__ __align__(256) __half g_combWh[HID * HID];
__device__ __align__(256) __half g_gWih16[3 * HID * HID];
__device__ __align__(256) __half g_gWhh16[3 * HID * HID];
__device__ __align__(256) __half g_ctxT[(size_t)HID * WW];

__device__ __align__(16) float g_u[OUTD];
__device__ __align__(16) float g_hdecB[2][HID];
__device__ __align__(16) float g_comb[HID];
__device__ __align__(16) float g_v2[HID + OUTD];
__device__ float g_sch[WW];

__device__ unsigned g_bcnt = 0;
__device__ volatile unsigned g_bgen = 0;
__device__ unsigned g_bcH[2] = {0, 0};
__device__ volatile unsigned g_bgH[2] = {0, 0};

__device__ __forceinline__ void gbar(unsigned nctas) {
    __syncthreads();
    if (threadIdx.x == 0) {
        __threadfence();
        unsigned gen = g_bgen;
        if (atomicAdd(&g_bcnt, 1u) == nctas - 1u) {
            g_bcnt = 0;
            __threadfence();
            g_bgen = gen + 1u;
        } else {
            while (g_bgen == gen) __nanosleep(32);
        }
        __threadfence();
    }
    __syncthreads();
}

__device__ __forceinline__ float tanh_ap(float x) {
    float y;
    asm("tanh.approx.f32 %0, %1;" : "=f"(y) : "f"(x));
    return y;
}
__device__ __forceinline__ float sig_ap(float x) {
    return fmaf(tanh_ap(0.5f * x), 0.5f, 0.5f);
}
__device__ __forceinline__ float sigf(float x)  { return __fdividef(1.f, 1.f + __expf(-x)); }
__device__ __forceinline__ float tanhf_fast(float x) { return 1.f - __fdividef(2.f, __expf(2.f * x) + 1.f); }
__device__ __forceinline__ float warp_red(float s) {
#pragma unroll
    for (int o = 16; o; o >>= 1) s += __shfl_down_sync(0xffffffffu, s, o);
    return s;
}

// fp16-weight x fp32-vector dot, length 1024, lane-strided
__device__ __forceinline__ float dot1024(const __half* __restrict__ w,
                                         const float* __restrict__ v, int lane) {
    float s = 0.f;
    const uint4* w4 = (const uint4*)w;
#pragma unroll
    for (int k = lane; k < 128; k += 32) {
        uint4 u = w4[k];
        const float4* vv = (const float4*)(v + (k << 3));
        float4 va = vv[0], vb = vv[1];
        float2 f0 = __half22float2(*(__half2*)&u.x);
        float2 f1 = __half22float2(*(__half2*)&u.y);
        float2 f2 = __half22float2(*(__half2*)&u.z);
        float2 f3 = __half22float2(*(__half2*)&u.w);
        s += f0.x * va.x + f0.y * va.y + f1.x * va.z + f1.y * va.w
           + f2.x * vb.x + f2.y * vb.y + f3.x * vb.z + f3.y * vb.w;
    }
    return s;
}

// ---------------------------------------------------------------------------
// fragment machinery (32m x 32n warp tile, single-pass fp16)
// ---------------------------------------------------------------------------
struct Frag {
    uint32_t ah[2][4], bh[4][2];
};

__device__ __forceinline__ void load_frags(Frag& f, uint32_t Ah, uint32_t Bh,
                                           int ks, int wr, int wc, int lane) {
#pragma unroll
    for (int mt = 0; mt < 2; mt++) {
        int r = wr * 32 + mt * 16 + (lane & 15);
        uint32_t ch = ((uint32_t)((ks * 2 + (lane >> 4)) ^ (r & 7))) << 4;
        LDSM4(f.ah[mt], Ah + r * 128 + ch);
    }
#pragma unroll
    for (int gp = 0; gp < 2; gp++) {
        int rn = (gp * 2 + (lane >> 4)) * 16 + wc * 8 + (lane & 7);
        uint32_t ch = ((uint32_t)((ks * 2 + ((lane >> 3) & 1)) ^ (rn & 7))) << 4;
        LDSM4(&f.bh[gp * 2][0], Bh + rn * 128 + ch);
    }
}

__device__ __forceinline__ void do_mmas(float (&acc)[2][4][4], const Frag& f) {
#pragma unroll
    for (int mt = 0; mt < 2; mt++)
#pragma unroll
        for (int q = 0; q < 4; q++)
            MMA16816(acc[mt][q], f.ah[mt], f.bh[q]);
}

// ---------------------------------------------------------------------------
// init / convert
// ---------------------------------------------------------------------------
__global__ void k_init(const float* __restrict__ bih, const float* __restrict__ bhh) {
    int i = blockIdx.x * blockDim.x + threadIdx.x;
    int n = MPAD * HID;
    __half z = __float2half(0.f);
    for (int j = i; j < n; j += gridDim.x * blockDim.x) {
        g_h[0][j] = z; g_h[1][j] = z;
    }
    if (i < 4 * HID) g_bias[i] = bih[i] + bhh[i];
    if (i < 2) { g_bcH[i] = 0; g_bgH[i] = 0; }
    if (i == 2) { g_bcnt = 0; g_bgen = 0; }
}

__global__ void k_conv_w(const float* __restrict__ Whh, const float* __restrict__ Wih) {
    size_t i = (size_t)blockIdx.x * blockDim.x + threadIdx.x;
    if (i >= (size_t)4096 * KTOT) return;
    int r = (int)(i / KTOT);
    int k = (int)(i % KTOT);
    float v = (k < HID) ? Whh[(size_t)r * HID + k] : Wih[(size_t)r * INPUTD + (k - HID)];
    g_W[i] = __float2half(v);
}

__global__ void k_conv_x(const float* __restrict__ data) {
    size_t i = (size_t)blockIdx.x * blockDim.x + threadIdx.x;
    if (i >= (size_t)T_STEPS * MPAD * INPUTD) return;
    int k = (int)(i % INPUTD);
    int b = (int)((i / INPUTD) % MPAD);
    int t = (int)(i / ((size_t)MPAD * INPUTD));
    float v = (b < BATCH) ? data[((size_t)t * BATCH + b) * INPUTD + k] : 0.f;
    g_x[i] = __float2half(v);
}

__global__ void k_conv_dec(const float* __restrict__ attn_W, const float* __restrict__ comb_W,
                           const float* __restrict__ gWih, const float* __restrict__ gWhh) {
    size_t i = (size_t)blockIdx.x * blockDim.x + threadIdx.x;
    const size_t nA = (size_t)WW * HID;
    const size_t nC = (size_t)HID * HID;
    const size_t nG = (size_t)3 * HID * HID;
    if (i < nA) {
        size_t j = i / HID, k = i % HID;
        g_attnWh[i] = __float2half(attn_W[j * (HID + OUTD) + OUTD + k]);
        return;
    }
    i -= nA;
    if (i < nC) {
        size_t r = i / HID, k = i % HID;
        g_combWh[i] = __float2half(comb_W[r * (HID + OUTD) + OUTD + k]);
        return;
    }
    i -= nC;
    if (i < nG) { g_gWih16[i] = __float2half(gWih[i]); return; }
    i -= nG;
    if (i < nG) { g_gWhh16[i] = __float2half(gWhh[i]); return; }
}

// ---------------------------------------------------------------------------
// k_enc: persistent, 240 LSTM steps, weights resident, c in registers,
// split-phase barrier. Activations via MUFU tanh.approx.
// ---------------------------------------------------------------------------
__global__ __launch_bounds__(256, 1) void k_enc() {
    extern __shared__ __align__(128) char smem[];
    const uint32_t sb  = smem_to_u32(smem);
    const uint32_t sbW = sb;
    const uint32_t sbA = sb + SMW;
    const int tid  = threadIdx.x;
    const int lane = tid & 31;
    const int wid  = tid >> 5;
    const int wr   = wid & 3;
    const int wc   = wid >> 2;
    const int n0   = (blockIdx.x & 63) * 16;
    const int mh   = blockIdx.x >> 6;
    const int m0   = mh * 128;
    const int rowq = lane >> 2;
    const int col2 = (lane & 3) * 2;

    // resident W: 20 K64 tiles x 8KB (K128 chunk ci at ci*16384)
    for (int i = tid; i < 10240; i += 256) {
        int ci = i >> 9, r = (i >> 3) & 63, ch = i & 7;
        int wrow = (r >> 4) * HID + n0 + (r & 15);
        size_t off = (size_t)wrow * KTOT + ci * 64 + ch * 8;
        uint32_t dst = sbW + ci * 8192 + r * 128 + (((uint32_t)(ch ^ (r & 7))) << 4);
        CP_ASYNC16(dst, g_W + off);
    }
    CP_COMMIT();

    int lb = 0, cbuf = 0;

    auto loadX2 = [&](int t, int j) {
        uint32_t base = sbA + lb * 32768; lb ^= 1;
#pragma unroll
        for (int s = 0; s < 2; s++) {
            int k0 = j * 128 + s * 64;
#pragma unroll
            for (int i = tid; i < 1024; i += 256) {
                int r = i >> 3, ch = i & 7;
                size_t off = ((size_t)t * MPAD + m0 + r) * INPUTD + k0 + ch * 8;
                CP_ASYNC16(base + s * 16384 + r * 128 + (((uint32_t)(ch ^ (r & 7))) << 4),
                           g_x + off);
            }
        }
        CP_COMMIT();
    };
    auto loadH2 = [&](const __half* hIn, int c) {
        uint32_t base = sbA + lb * 32768; lb ^= 1;
#pragma unroll
        for (int s = 0; s < 2; s++) {
            int k0 = c * 128 + s * 64;
#pragma unroll
            for (int i = tid; i < 1024; i += 256) {
                int r = i >> 3, ch = i & 7;
                size_t off = (size_t)(m0 + r) * HID + k0 + ch * 8;
                CP_ASYNC16(base + s * 16384 + r * 128 + (((uint32_t)(ch ^ (r & 7))) << 4),
                           hIn + off);
            }
        }
        CP_COMMIT();
    };

    float acc[2][4][4];
    float creg[2][2][2];
#pragma unroll
    for (int a = 0; a < 2; a++)
#pragma unroll
        for (int b = 0; b < 2; b++)
#pragma unroll
            for (int d = 0; d < 2; d++) creg[a][b][d] = 0.f;
#pragma unroll
    for (int mt = 0; mt < 2; mt++)
#pragma unroll
        for (int q = 0; q < 4; q++)
#pragma unroll
            for (int j = 0; j < 4; j++) acc[mt][q][j] = 0.f;

    auto computeChunk = [&](int wchunk) {
        uint32_t Ab = sbA + cbuf * 32768; cbuf ^= 1;
        uint32_t Bb = sbW + wchunk * 16384;
        Frag fr[2];
        load_frags(fr[0], Ab, Bb, 0, wr, wc, lane);
#pragma unroll
        for (int ks = 0; ks < 8; ks++) {
            if (ks < 7) {
                int kn = ks + 1;
                load_frags(fr[kn & 1], Ab + (kn >> 2) * 16384, Bb + (kn >> 2) * 8192,
                           kn & 3, wr, wc, lane);
            }
            do_mmas(acc, fr[ks & 1]);
        }
    };

    unsigned snap = 0;

    // prologue
    loadX2(0, 0); loadX2(0, 1);
    CP_WAIT1(); __syncthreads(); computeChunk(8);
    loadH2(g_h[0], 0);
    CP_WAIT1(); __syncthreads(); computeChunk(9);
    loadH2(g_h[0], 1);

    for (int t = 0; t < T_STEPS; t++) {
        const __half* __restrict__ hIn = g_h[t & 1];

        for (int c = 0; c < 8; c++) {
            if (t == T_STEPS - 1 && c == 7) { CP_WAIT0(); } else { CP_WAIT1(); }
            __syncthreads();
            computeChunk(c);
            if (c < 6)                loadH2(hIn, c + 2);
            else if (t + 1 < T_STEPS) loadX2(t + 1, c - 6);
        }

        // fused LSTM gate epilogue (c in registers, MUFU tanh)
        __half* __restrict__ hOut = g_h[(t + 1) & 1];
#pragma unroll
        for (int mt = 0; mt < 2; mt++)
#pragma unroll
            for (int rp = 0; rp < 2; rp++) {
                int m = m0 + wr * 32 + mt * 16 + rowq + rp * 8;
                if (m < BATCH) {
                    int n = n0 + wc * 8 + col2;
                    size_t idx = (size_t)m * HID + n;
                    float2 bi = *(const float2*)&g_bias[n];
                    float2 bf = *(const float2*)&g_bias[HID + n];
                    float2 bg = *(const float2*)&g_bias[2 * HID + n];
                    float2 bo = *(const float2*)&g_bias[3 * HID + n];
                    float h[2];
#pragma unroll
                    for (int j = 0; j < 2; j++) {
                        float gi = acc[mt][0][rp * 2 + j] + (j ? bi.y : bi.x);
                        float gf = acc[mt][1][rp * 2 + j] + (j ? bf.y : bf.x);
                        float gg = acc[mt][2][rp * 2 + j] + (j ? bg.y : bg.x);
                        float go = acc[mt][3][rp * 2 + j] + (j ? bo.y : bo.x);
                        float cn = sig_ap(gf) * creg[mt][rp][j] + sig_ap(gi) * tanh_ap(gg);
                        creg[mt][rp][j] = cn;
                        h[j] = sig_ap(go) * tanh_ap(cn);
                    }
                    *(__half2*)&hOut[idx] =
                        __halves2half2(__float2half(h[0]), __float2half(h[1]));
                }
            }

        if (t + 1 == T_STEPS) break;

        // ARRIVE
        __threadfence();
        __syncthreads();
        if (tid == 0) {
            snap = g_bgH[mh];
            if (atomicAdd(&g_bcH[mh], 1u) == 63u) {
                g_bcH[mh] = 0;
                __threadfence();
                g_bgH[mh] = snap + 1u;
            }
        }

#pragma unroll
        for (int mt = 0; mt < 2; mt++)
#pragma unroll
            for (int q = 0; q < 4; q++)
#pragma unroll
                for (int j = 0; j < 4; j++) acc[mt][q][j] = 0.f;

        CP_WAIT1(); __syncthreads(); computeChunk(8);

        // WAIT
        if (tid == 0) {
            while (g_bgH[mh] == snap) __nanosleep(32);
            __threadfence();
        }
        __syncthreads();

        const __half* __restrict__ hN = g_h[(t + 1) & 1];
        loadH2(hN, 0);
        CP_WAIT1(); __syncthreads(); computeChunk(9);
        loadH2(hN, 1);
    }
}

// ---------------------------------------------------------------------------
// k_dec: persistent decoder, 64 CTAs x 512 thr (16 warps), 4 barriers/step.
// ---------------------------------------------------------------------------
__global__ __launch_bounds__(512, 1) void k_dec(
    const float* __restrict__ attn_W, const float* __restrict__ attn_b,
    const float* __restrict__ comb_W, const float* __restrict__ comb_b,
    const float* __restrict__ gbih,   const float* __restrict__ gbhh,
    const float* __restrict__ out_W,  const float* __restrict__ out_b,
    float* __restrict__ outp)
{
    __shared__ float s_aw[WW];
    __shared__ float rbuf[16];
    __shared__ float lg[OUTD];
    __shared__ float s_g[96];

    const int tid  = threadIdx.x;
    const int bid  = blockIdx.x;
    const int lane = tid & 31;
    const int warp = tid >> 5;           // 0..15
    const int gw   = bid * 16 + warp;    // 0..1023
    const int gt   = bid * 512 + tid;

    if (gt < HID) g_hdecB[0][gt] = __half2float(g_h[0][(size_t)(BATCH - 1) * HID + gt]);
    if (gt < OUTD) g_u[gt] = 0.125f;
    for (size_t i = gt; i < (size_t)WW * HID; i += NCTA_D * 512) {
        size_t j = i / HID, n = i % HID;
        g_ctxT[n * WW + j] = g_h[0][j * HID + n];
    }
    gbar(NCTA_D);

    auto out_head = [&](int sidx, const float* hv) {
        if (warp < OUTD) {
            const float4* row = (const float4*)(out_W + (size_t)warp * HID);
            const float4* v   = (const float4*)hv;
            float s = 0.f;
            for (int k = lane; k < HID / 4; k += 32) {
                float4 w = row[k], x = v[k];
                s += w.x * x.x + w.y * x.y + w.z * x.z + w.w * x.w;
            }
            s = warp_red(s);
            if (!lane) lg[warp] = s + out_b[warp];
        }
        __syncthreads();
        if (tid == 0) {
            float mx = -1e30f;
#pragma unroll
            for (int i = 0; i < OUTD; i++) mx = fmaxf(mx, lg[i]);
            float sum = 0.f;
#pragma unroll
            for (int i = 0; i < OUTD; i++) sum += __expf(lg[i] - mx);
            float lse = mx + __logf(sum);
#pragma unroll
            for (int i = 0; i < OUTD; i++) {
                float lp = lg[i] - lse;
                outp[sidx * OUTD + i] = lp;
                g_u[i] = lp;
            }
        }
        __syncthreads();
    };

    for (int s = 0; s < NSTEPS; s++) {
        const float* __restrict__ hcur = g_hdecB[s & 1];
        float* __restrict__ hnxt       = g_hdecB[(s + 1) & 1];

        // P1: CTA0 -> prev output head; other CTAs -> attn scores (h part)
        if (bid == 0) {
            if (s > 0) out_head(s - 1, hcur);
        } else {
            int j = gw - 16;
            if (j < WW) {
                float x = dot1024(g_attnWh + (size_t)j * HID, hcur, lane);
                x = warp_red(x);
                if (!lane) g_sch[j] = x;
            }
        }
        gbar(NCTA_D);

        // P2: per-CTA redundant softmax + applied columns (1 col/warp)
        {
            float x;
            if (tid < WW) {
                float su = 0.f;
#pragma unroll
                for (int k = 0; k < OUTD; k++)
                    su += g_u[k] * attn_W[(size_t)tid * (HID + OUTD) + k];
                x = g_sch[tid] + su + attn_b[tid];
            } else x = -1e30f;
            float mx = x;
#pragma unroll
            for (int o = 16; o; o >>= 1) mx = fmaxf(mx, __shfl_xor_sync(0xffffffffu, mx, o));
            if (!lane) rbuf[warp] = mx;
            __syncthreads();
            float bm = rbuf[0];
#pragma unroll
            for (int i = 1; i < 16; i++) bm = fmaxf(bm, rbuf[i]);
            float e = (tid < WW) ? __expf(x - bm) : 0.f;
            float sm = e;
#pragma unroll
            for (int o = 16; o; o >>= 1) sm += __shfl_xor_sync(0xffffffffu, sm, o);
            __syncthreads();
            if (!lane) rbuf[warp] = sm;
            __syncthreads();
            float tot = 0.f;
#pragma unroll
            for (int i = 0; i < 16; i++) tot += rbuf[i];
            if (tid < WW) s_aw[tid] = e / tot;
            __syncthreads();
            {
                int n = gw;
                const __half* ct = g_ctxT + (size_t)n * WW;
                float a = 0.f;
                for (int j = lane; j < WW; j += 32) a += s_aw[j] * __half2float(ct[j]);
                a = warp_red(a);
                if (!lane) g_v2[OUTD + n] = a;
            }
            if (bid == 0 && tid < OUTD) g_v2[tid] = g_u[tid];
        }
        gbar(NCTA_D);

        // P3: comb = relu(comb_W @ [u; applied] + b)  (1 row/warp)
        {
            int r = gw;
            float x = dot1024(g_combWh + (size_t)r * HID, g_v2 + OUTD, lane);
            x = warp_red(x);
            if (!lane) {
                float su = 0.f;
#pragma unroll
                for (int k = 0; k < OUTD; k++)
                    su += comb_W[(size_t)r * (HID + OUTD) + k] * g_v2[k];
                g_comb[r] = fmaxf(x + su + comb_b[r], 0.f);
            }
        }
        gbar(NCTA_D);

        // P4+P5: CTA-local 96 GRU rows -> smem, update 16 hdec entries
        for (int idx = warp; idx < 96; idx += 16) {
            int p = idx >> 4, i = idx & 15;
            int n = bid * 16 + i;
            float x;
            if (p < 3) x = dot1024(g_gWih16 + ((size_t)p * HID + n) * HID, g_comb, lane);
            else       x = dot1024(g_gWhh16 + ((size_t)(p - 3) * HID + n) * HID, hcur, lane);
            x = warp_red(x);
            if (!lane) {
                if (p < 3) s_g[idx] = x + gbih[p * HID + n];
                else       s_g[idx] = x + gbhh[(p - 3) * HID + n];
            }
        }
        __syncthreads();
        if (tid < 16) {
            int n = bid * 16 + tid;
            float r  = sigf(s_g[tid] + s_g[48 + tid]);
            float z  = sigf(s_g[16 + tid] + s_g[64 + tid]);
            float nn = tanhf_fast(s_g[32 + tid] + r * s_g[80 + tid]);
            hnxt[n] = (1.f - z) * nn + z * hcur[n];
        }
        gbar(NCTA_D);
    }

    if (bid == 0) out_head(NSTEPS - 1, g_hdecB[NSTEPS & 1]);
}

// ---------------------------------------------------------------------------
// launch
// ---------------------------------------------------------------------------
extern "C" void kernel_launch(void* const* d_in, const int* in_sizes, int n_in,
                              void* d_out, int out_size) {
    const float* data     = (const float*)d_in[0];
    const float* enc_Wih  = (const float*)d_in[1];
    const float* enc_Whh  = (const float*)d_in[2];
    const float* enc_bih  = (const float*)d_in[3];
    const float* enc_bhh  = (const float*)d_in[4];
    const float* attn_W   = (const float*)d_in[5];
    const float* attn_b   = (const float*)d_in[6];
    const float* comb_W   = (const float*)d_in[7];
    const float* comb_b   = (const float*)d_in[8];
    const float* gru_Wih  = (const float*)d_in[9];
    const float* gru_Whh  = (const float*)d_in[10];
    const float* gru_bih  = (const float*)d_in[11];
    const float* gru_bhh  = (const float*)d_in[12];
    const float* out_W    = (const float*)d_in[13];
    const float* out_b    = (const float*)d_in[14];
    float* out = (float*)d_out;

    cudaFuncSetAttribute(k_enc, cudaFuncAttributeMaxDynamicSharedMemorySize, SMEMB);

    k_init<<<1024, 256>>>(enc_bih, enc_bhh);
    k_conv_w<<<(4096 * KTOT + 255) / 256, 256>>>(enc_Whh, enc_Wih);
    k_conv_x<<<(T_STEPS * MPAD * INPUTD + 255) / 256, 256>>>(data);
    {
        size_t ntot = (size_t)WW * HID + (size_t)HID * HID + 2 * (size_t)3 * HID * HID;
        k_conv_dec<<<(int)((ntot + 255) / 256), 256>>>(attn_W, comb_W, gru_Wih, gru_Whh);
    }

    k_enc<<<NCTA, 256, SMEMB>>>();

    k_dec<<<NCTA_D, 512>>>(attn_W, attn_b, comb_W, comb_b,
                           gru_bih, gru_bhh, out_W, out_b, out);
}